// round 1
// baseline (speedup 1.0000x reference)
#include <cuda_runtime.h>

#define N_NODES 50000
#define D 128
#define E_EDGES 600000
#define P_PAIRS 131072
#define O_OUT 7

// Scratch (device globals: no allocation allowed in kernel_launch)
__device__ float g_agg[N_NODES * D];
__device__ float g_t[N_NODES * D];
__device__ float g_h[N_NODES * D];
__device__ float g_colsum[D];
__device__ float g_colsq[D];
__device__ float g_bn[2 * D];   // [0:128) scale a, [128:256) shift c

// ---------------------------------------------------------------------------
// Zero agg + column stats
// ---------------------------------------------------------------------------
__global__ void k_zero() {
    int i = blockIdx.x * blockDim.x + threadIdx.x;   // 1 float4 each
    float4 z = make_float4(0.f, 0.f, 0.f, 0.f);
    if (i < N_NODES * D / 4)
        reinterpret_cast<float4*>(g_agg)[i] = z;
    if (blockIdx.x == 0 && threadIdx.x < D) {
        g_colsum[threadIdx.x] = 0.f;
        g_colsq[threadIdx.x] = 0.f;
    }
}

// ---------------------------------------------------------------------------
// Edge scatter: agg[dst] += h[src]   (warp per edge, float4 per lane)
// ---------------------------------------------------------------------------
__global__ void k_scatter(const float* __restrict__ h,
                          const int* __restrict__ src,
                          const int* __restrict__ dst) {
    int e = (blockIdx.x * blockDim.x + threadIdx.x) >> 5;
    int lane = threadIdx.x & 31;
    if (e >= E_EDGES) return;
    int s = src[e];
    int d = dst[e];
    float4 v = reinterpret_cast<const float4*>(h + (size_t)s * D)[lane];
    float* o = g_agg + (size_t)d * D + lane * 4;
    atomicAdd(o + 0, v.x);
    atomicAdd(o + 1, v.y);
    atomicAdd(o + 2, v.z);
    atomicAdd(o + 3, v.w);
}

// ---------------------------------------------------------------------------
// GEMM: out[i][j] = relu( sum_k A[i][k] * W[j][k] + bias[j] )
// COMBINE=1: A[i][k] = (1+eps)*in[i][k] + g_agg[i][k]
// 128x128 tile (BN = full D), BK=8, 256 threads, 8x8 microtile
// ---------------------------------------------------------------------------
template <int COMBINE>
__global__ void __launch_bounds__(256) k_gemm(const float* __restrict__ A,
                                              const float* __restrict__ W,
                                              const float* __restrict__ bias,
                                              float* __restrict__ out,
                                              const float* __restrict__ epsp) {
    __shared__ float As[8][128];
    __shared__ float Bs[8][128];

    const int t = threadIdx.x;          // 0..255
    const int tx = t & 15;              // col group
    const int ty = t >> 4;              // row group
    const int row0 = blockIdx.x * 128;

    float cA = 1.0f;
    if (COMBINE) cA = 1.0f + *epsp;

    const int lrow = t >> 1;            // 0..127 row/col of the staged tile
    const int lk4 = (t & 1) * 4;        // 0 or 4

    float acc[8][8];
#pragma unroll
    for (int i = 0; i < 8; i++)
#pragma unroll
        for (int j = 0; j < 8; j++) acc[i][j] = 0.f;

    for (int k0 = 0; k0 < 128; k0 += 8) {
        // stage loads from global
        float4 a4 = make_float4(0.f, 0.f, 0.f, 0.f);
        int gr = row0 + lrow;
        if (gr < N_NODES) {
            a4 = *reinterpret_cast<const float4*>(A + (size_t)gr * D + k0 + lk4);
            if (COMBINE) {
                float4 q = *reinterpret_cast<const float4*>(g_agg + (size_t)gr * D + k0 + lk4);
                a4.x = cA * a4.x + q.x;
                a4.y = cA * a4.y + q.y;
                a4.z = cA * a4.z + q.z;
                a4.w = cA * a4.w + q.w;
            }
        }
        float4 b4 = *reinterpret_cast<const float4*>(W + (size_t)lrow * D + k0 + lk4);

        __syncthreads();
        As[lk4 + 0][lrow] = a4.x;
        As[lk4 + 1][lrow] = a4.y;
        As[lk4 + 2][lrow] = a4.z;
        As[lk4 + 3][lrow] = a4.w;
        Bs[lk4 + 0][lrow] = b4.x;
        Bs[lk4 + 1][lrow] = b4.y;
        Bs[lk4 + 2][lrow] = b4.z;
        Bs[lk4 + 3][lrow] = b4.w;
        __syncthreads();

#pragma unroll
        for (int kk = 0; kk < 8; kk++) {
            float4 a0 = *reinterpret_cast<float4*>(&As[kk][ty * 8]);
            float4 a1 = *reinterpret_cast<float4*>(&As[kk][ty * 8 + 4]);
            float4 b0 = *reinterpret_cast<float4*>(&Bs[kk][tx * 8]);
            float4 b1 = *reinterpret_cast<float4*>(&Bs[kk][tx * 8 + 4]);
            float a[8] = {a0.x, a0.y, a0.z, a0.w, a1.x, a1.y, a1.z, a1.w};
            float b[8] = {b0.x, b0.y, b0.z, b0.w, b1.x, b1.y, b1.z, b1.w};
#pragma unroll
            for (int i = 0; i < 8; i++)
#pragma unroll
                for (int j = 0; j < 8; j++) acc[i][j] += a[i] * b[j];
        }
    }

    // epilogue: bias + relu + store
    float bj[8];
#pragma unroll
    for (int j = 0; j < 8; j++) bj[j] = bias[tx * 8 + j];

#pragma unroll
    for (int i = 0; i < 8; i++) {
        int gr = row0 + ty * 8 + i;
        if (gr < N_NODES) {
            float4 o0, o1;
            o0.x = fmaxf(acc[i][0] + bj[0], 0.f);
            o0.y = fmaxf(acc[i][1] + bj[1], 0.f);
            o0.z = fmaxf(acc[i][2] + bj[2], 0.f);
            o0.w = fmaxf(acc[i][3] + bj[3], 0.f);
            o1.x = fmaxf(acc[i][4] + bj[4], 0.f);
            o1.y = fmaxf(acc[i][5] + bj[5], 0.f);
            o1.z = fmaxf(acc[i][6] + bj[6], 0.f);
            o1.w = fmaxf(acc[i][7] + bj[7], 0.f);
            *reinterpret_cast<float4*>(out + (size_t)gr * D + tx * 8) = o0;
            *reinterpret_cast<float4*>(out + (size_t)gr * D + tx * 8 + 4) = o1;
        }
    }
}

// ---------------------------------------------------------------------------
// Column sum / sumsq over N rows (strided so each thread stays on one column)
// ---------------------------------------------------------------------------
__global__ void k_colstats(const float* __restrict__ h) {
    __shared__ float ssum[D];
    __shared__ float ssq[D];
    int t = threadIdx.x;
    if (t < D) { ssum[t] = 0.f; ssq[t] = 0.f; }
    __syncthreads();

    long long idx = (long long)blockIdx.x * blockDim.x + t;
    long long stride = (long long)gridDim.x * blockDim.x;   // multiple of 128
    int col = (int)(idx & (D - 1));
    float s = 0.f, q = 0.f;
    for (; idx < (long long)N_NODES * D; idx += stride) {
        float v = h[idx];
        s += v;
        q += v * v;
    }
    atomicAdd(&ssum[col], s);
    atomicAdd(&ssq[col], q);
    __syncthreads();
    if (t < D) {
        atomicAdd(&g_colsum[t], ssum[t]);
        atomicAdd(&g_colsq[t], ssq[t]);
    }
}

// ---------------------------------------------------------------------------
// BN scale/shift prep (1 block, 128 threads)
// ---------------------------------------------------------------------------
__global__ void k_bnprep(const float* __restrict__ gamma,
                         const float* __restrict__ beta) {
    int t = threadIdx.x;
    float inv_n = 1.0f / (float)N_NODES;
    float mu = g_colsum[t] * inv_n;
    float var = g_colsq[t] * inv_n - mu * mu;
    float a = gamma[t] * rsqrtf(var + 1e-5f);
    g_bn[t] = a;
    g_bn[D + t] = beta[t] - mu * a;
}

// ---------------------------------------------------------------------------
// Apply BN affine in place
// ---------------------------------------------------------------------------
__global__ void k_bnapply(float* __restrict__ h) {
    int i = blockIdx.x * blockDim.x + threadIdx.x;   // float4 index
    if (i >= N_NODES * D / 4) return;
    int c = (i * 4) & (D - 1);
    float4 v = reinterpret_cast<float4*>(h)[i];
    v.x = g_bn[c + 0] * v.x + g_bn[D + c + 0];
    v.y = g_bn[c + 1] * v.y + g_bn[D + c + 1];
    v.z = g_bn[c + 2] * v.z + g_bn[D + c + 2];
    v.w = g_bn[c + 3] * v.w + g_bn[D + c + 3];
    reinterpret_cast<float4*>(h)[i] = v;
}

// ---------------------------------------------------------------------------
// Pair head: out[p] = (h[i0] * h[i1]) @ Wfc.T + bfc   (warp per pair)
// ---------------------------------------------------------------------------
__global__ void __launch_bounds__(256) k_pairs(const float* __restrict__ h,
                                               const int* __restrict__ pairs,
                                               const float* __restrict__ Wfc,
                                               const float* __restrict__ bfc,
                                               float* __restrict__ out) {
    __shared__ float sW[O_OUT][D];
    __shared__ float sb[O_OUT];
    int t = threadIdx.x;
    for (int i = t; i < O_OUT * D; i += 256) sW[i / D][i % D] = Wfc[i];
    if (t < O_OUT) sb[t] = bfc[t];
    __syncthreads();

    int p = (blockIdx.x * 256 + t) >> 5;
    int lane = t & 31;
    if (p >= P_PAIRS) return;

    int i0 = pairs[2 * p];
    int i1 = pairs[2 * p + 1];
    float4 u = reinterpret_cast<const float4*>(h + (size_t)i0 * D)[lane];
    float4 v = reinterpret_cast<const float4*>(h + (size_t)i1 * D)[lane];
    float4 w = make_float4(u.x * v.x, u.y * v.y, u.z * v.z, u.w * v.w);

    float s[O_OUT];
#pragma unroll
    for (int o = 0; o < O_OUT; o++) {
        s[o] = w.x * sW[o][4 * lane + 0] + w.y * sW[o][4 * lane + 1] +
               w.z * sW[o][4 * lane + 2] + w.w * sW[o][4 * lane + 3];
    }
#pragma unroll
    for (int o = 0; o < O_OUT; o++) {
#pragma unroll
        for (int off = 16; off > 0; off >>= 1)
            s[o] += __shfl_xor_sync(0xffffffffu, s[o], off);
    }
    if (lane == 0) {
#pragma unroll
        for (int o = 0; o < O_OUT; o++) out[(size_t)p * O_OUT + o] = s[o] + sb[o];
    }
}

// ---------------------------------------------------------------------------
// Launch
// ---------------------------------------------------------------------------
extern "C" void kernel_launch(void* const* d_in, const int* in_sizes, int n_in,
                              void* d_out, int out_size) {
    const float* x    = (const float*)d_in[0];
    const float* W1a  = (const float*)d_in[1];
    const float* b1a  = (const float*)d_in[2];
    const float* W2a  = (const float*)d_in[3];
    const float* b2a  = (const float*)d_in[4];
    const float* g0   = (const float*)d_in[5];
    const float* bt0  = (const float*)d_in[6];
    const float* eps0 = (const float*)d_in[7];
    const float* W1b  = (const float*)d_in[8];
    const float* b1b  = (const float*)d_in[9];
    const float* W2b  = (const float*)d_in[10];
    const float* b2b  = (const float*)d_in[11];
    const float* g1   = (const float*)d_in[12];
    const float* bt1  = (const float*)d_in[13];
    const float* eps1 = (const float*)d_in[14];
    const float* Wl   = (const float*)d_in[15];
    const float* bl   = (const float*)d_in[16];
    const float* Wfc  = (const float*)d_in[17];
    const float* bfc  = (const float*)d_in[18];
    const int* esrc   = (const int*)d_in[19];
    const int* edst   = (const int*)d_in[20];
    const int* pairs  = (const int*)d_in[21];
    float* out = (float*)d_out;

    float *t, *h;
    cudaGetSymbolAddress((void**)&t, g_t);
    cudaGetSymbolAddress((void**)&h, g_h);

    const int ZB = (N_NODES * D / 4 + 255) / 256;           // 6250
    const int SB = (E_EDGES * 32 + 255) / 256;              // 75000
    const int GB = (N_NODES + 127) / 128;                   // 391
    const int PB = (P_PAIRS * 32) / 256;                    // 16384

    // Layer A
    k_zero<<<ZB, 256>>>();
    k_scatter<<<SB, 256>>>(x, esrc, edst);
    k_gemm<1><<<GB, 256>>>(x, W1a, b1a, t, eps0);
    k_gemm<0><<<GB, 256>>>(t, W2a, b2a, h, nullptr);
    k_colstats<<<2048, 256>>>(h);
    k_bnprep<<<1, 128>>>(g0, bt0);
    k_bnapply<<<ZB, 256>>>(h);

    // Layer B
    k_zero<<<ZB, 256>>>();
    k_scatter<<<SB, 256>>>(h, esrc, edst);
    k_gemm<1><<<GB, 256>>>(h, W1b, b1b, t, eps1);
    k_gemm<0><<<GB, 256>>>(t, W2b, b2b, h, nullptr);
    k_colstats<<<2048, 256>>>(h);
    k_bnprep<<<1, 128>>>(g1, bt1);
    k_bnapply<<<ZB, 256>>>(h);

    // Final linear + pair head
    k_gemm<0><<<GB, 256>>>(h, Wl, bl, t, nullptr);
    k_pairs<<<PB, 256>>>(t, pairs, Wfc, bfc, out);
}

// round 2
// speedup vs baseline: 1.6413x; 1.6413x over previous
#include <cuda_runtime.h>
#include <cuda_bf16.h>
#include <cstdint>

#define N_NODES 50000
#define D 128
#define E_EDGES 600000
#define P_PAIRS 131072
#define O_OUT 7

// smem layout for tensor GEMM: rows of 68 uint32 (136 bf16, 272 B)
#define ROW_U32 68
#define ARR_U32 (128 * ROW_U32)            // one 128x128 bf16 array (padded)
#define GEMM_SMEM_BYTES (4 * ARR_U32 * 4)  // As_hi, As_lo, Ws_hi, Ws_lo

// Scratch (device globals: no allocation allowed)
__device__ float g_agg[N_NODES * D];
__device__ float g_t[N_NODES * D];
__device__ float g_h[N_NODES * D];
__device__ float g_colsum[D];
__device__ float g_colsq[D];
__device__ float g_bn[2 * D];

// ---------------------------------------------------------------------------
__global__ void k_zero() {
    int i = blockIdx.x * blockDim.x + threadIdx.x;
    float4 z = make_float4(0.f, 0.f, 0.f, 0.f);
    if (i < N_NODES * D / 4)
        reinterpret_cast<float4*>(g_agg)[i] = z;
    if (blockIdx.x == 0 && threadIdx.x < D) {
        g_colsum[threadIdx.x] = 0.f;
        g_colsq[threadIdx.x] = 0.f;
    }
}

// ---------------------------------------------------------------------------
// Edge scatter: agg[dst] += h[src]  (warp/edge, red.global.add.v4.f32 per lane)
// ---------------------------------------------------------------------------
__global__ void k_scatter(const float* __restrict__ h,
                          const int* __restrict__ src,
                          const int* __restrict__ dst) {
    int e = (blockIdx.x * blockDim.x + threadIdx.x) >> 5;
    int lane = threadIdx.x & 31;
    if (e >= E_EDGES) return;
    int s = src[e];
    int d = dst[e];
    float4 v = reinterpret_cast<const float4*>(h + (size_t)s * D)[lane];
    float* o = g_agg + (size_t)d * D + lane * 4;
    asm volatile("red.global.add.v4.f32 [%0], {%1,%2,%3,%4};"
                 :: "l"(o), "f"(v.x), "f"(v.y), "f"(v.z), "f"(v.w)
                 : "memory");
}

// ---------------------------------------------------------------------------
// Tensor-core GEMM: out = relu(A @ W^T + bias), A is Mx128, W is 128x128.
// fp32 emulated via bf16 split: hi*hi + hi*lo + lo*hi, fp32 accum.
// Block: 128 rows x 128 cols, 256 threads (8 warps as 4M x 2N).
// COMBINE: A[i][k] = (1+eps)*in[i][k] + g_agg[i][k]
// ---------------------------------------------------------------------------
__device__ __forceinline__ uint32_t smem_u32(const void* p) {
    return (uint32_t)__cvta_generic_to_shared(p);
}

__device__ __forceinline__ void split2(float a, float b, uint32_t& hi, uint32_t& lo) {
    __nv_bfloat162 h = __floats2bfloat162_rn(a, b);
    float ra = a - __bfloat162float(h.x);
    float rb = b - __bfloat162float(h.y);
    __nv_bfloat162 l = __floats2bfloat162_rn(ra, rb);
    hi = *reinterpret_cast<uint32_t*>(&h);
    lo = *reinterpret_cast<uint32_t*>(&l);
}

__device__ __forceinline__ void ldmx4(uint32_t addr, uint32_t r[4]) {
    asm volatile("ldmatrix.sync.aligned.m8n8.x4.shared.b16 {%0,%1,%2,%3}, [%4];"
                 : "=r"(r[0]), "=r"(r[1]), "=r"(r[2]), "=r"(r[3]) : "r"(addr));
}

__device__ __forceinline__ void mma16816(float c[4], const uint32_t a[4],
                                         uint32_t b0, uint32_t b1) {
    asm volatile(
        "mma.sync.aligned.m16n8k16.row.col.f32.bf16.bf16.f32 "
        "{%0,%1,%2,%3},{%4,%5,%6,%7},{%8,%9},{%0,%1,%2,%3};"
        : "+f"(c[0]), "+f"(c[1]), "+f"(c[2]), "+f"(c[3])
        : "r"(a[0]), "r"(a[1]), "r"(a[2]), "r"(a[3]), "r"(b0), "r"(b1));
}

template <int COMBINE>
__global__ void __launch_bounds__(256) k_gemm_tc(const float* __restrict__ A,
                                                 const float* __restrict__ W,
                                                 const float* __restrict__ bias,
                                                 float* __restrict__ out,
                                                 const float* __restrict__ epsp) {
    extern __shared__ uint32_t smem[];
    uint32_t* As_hi = smem;
    uint32_t* As_lo = smem + ARR_U32;
    uint32_t* Ws_hi = smem + 2 * ARR_U32;
    uint32_t* Ws_lo = smem + 3 * ARR_U32;

    const int t = threadIdx.x;
    const int row0 = blockIdx.x * 128;
    float cA = 1.0f;
    if (COMBINE) cA = 1.0f + *epsp;

    // ---- stage: fp32 -> bf16 hi/lo into smem ----
    {
        int row = t >> 1;
        int j0 = (t & 1) * 16;
        int gr = row0 + row;
        const float4* Ar = reinterpret_cast<const float4*>(A + (size_t)gr * D);
        const float4* Gr = reinterpret_cast<const float4*>(g_agg + (size_t)gr * D);
        const float4* Wr = reinterpret_cast<const float4*>(W + (size_t)row * D);
#pragma unroll 4
        for (int j = 0; j < 16; j++) {
            int f4 = j0 + j;
            float4 v = make_float4(0.f, 0.f, 0.f, 0.f);
            if (gr < N_NODES) {
                v = Ar[f4];
                if (COMBINE) {
                    float4 q = Gr[f4];
                    v.x = cA * v.x + q.x;
                    v.y = cA * v.y + q.y;
                    v.z = cA * v.z + q.z;
                    v.w = cA * v.w + q.w;
                }
            }
            uint32_t h0, l0, h1, l1;
            split2(v.x, v.y, h0, l0);
            split2(v.z, v.w, h1, l1);
            int o = row * ROW_U32 + f4 * 2;
            *reinterpret_cast<uint2*>(&As_hi[o]) = make_uint2(h0, h1);
            *reinterpret_cast<uint2*>(&As_lo[o]) = make_uint2(l0, l1);

            float4 w = Wr[f4];
            split2(w.x, w.y, h0, l0);
            split2(w.z, w.w, h1, l1);
            *reinterpret_cast<uint2*>(&Ws_hi[o]) = make_uint2(h0, h1);
            *reinterpret_cast<uint2*>(&Ws_lo[o]) = make_uint2(l0, l1);
        }
    }
    __syncthreads();

    // ---- compute ----
    const int warp = t >> 5;
    const int lane = t & 31;
    const int wm = warp >> 1;   // 0..3 : rows wm*32
    const int wn = warp & 1;    // 0..1 : cols wn*64

    // ldmatrix byte offsets (within an array), per k-step add ks*32
    uint32_t aoff[2], boff[4];
#pragma unroll
    for (int mt = 0; mt < 2; mt++) {
        int row = wm * 32 + mt * 16 + ((lane >> 3) & 1) * 8 + (lane & 7);
        aoff[mt] = row * (ROW_U32 * 4) + (lane >> 4) * 16;
    }
#pragma unroll
    for (int np = 0; np < 4; np++) {
        int row = wn * 64 + np * 16 + (lane >> 4) * 8 + (lane & 7);
        boff[np] = row * (ROW_U32 * 4) + ((lane >> 3) & 1) * 16;
    }

    const uint32_t Ahi = smem_u32(As_hi), Alo = smem_u32(As_lo);
    const uint32_t Bhi = smem_u32(Ws_hi), Blo = smem_u32(Ws_lo);
    uint32_t abase[3] = {Ahi, Ahi, Alo};
    uint32_t bbase[3] = {Bhi, Blo, Bhi};

    float acc[2][8][4];
#pragma unroll
    for (int mt = 0; mt < 2; mt++)
#pragma unroll
        for (int nt = 0; nt < 8; nt++)
#pragma unroll
            for (int i = 0; i < 4; i++) acc[mt][nt][i] = 0.f;

    for (int pass = 0; pass < 3; pass++) {
        uint32_t ab = abase[pass], bb = bbase[pass];
#pragma unroll
        for (int ks = 0; ks < 8; ks++) {
            uint32_t kb = ks * 32;
            uint32_t areg[2][4], breg[4][4];
#pragma unroll
            for (int mt = 0; mt < 2; mt++) ldmx4(ab + aoff[mt] + kb, areg[mt]);
#pragma unroll
            for (int np = 0; np < 4; np++) ldmx4(bb + boff[np] + kb, breg[np]);
#pragma unroll
            for (int mt = 0; mt < 2; mt++)
#pragma unroll
                for (int nt = 0; nt < 8; nt++) {
                    int np = nt >> 1, o = (nt & 1) * 2;
                    mma16816(acc[mt][nt], areg[mt], breg[np][o], breg[np][o + 1]);
                }
        }
    }

    // ---- epilogue: bias + relu + store ----
    const int g = lane >> 2;
    const int c2 = (lane & 3) * 2;
#pragma unroll
    for (int nt = 0; nt < 8; nt++) {
        int col = wn * 64 + nt * 8 + c2;
        float b0 = __ldg(bias + col);
        float b1 = __ldg(bias + col + 1);
#pragma unroll
        for (int mt = 0; mt < 2; mt++) {
            int ra = row0 + wm * 32 + mt * 16 + g;
            if (ra < N_NODES) {
                float2 v;
                v.x = fmaxf(acc[mt][nt][0] + b0, 0.f);
                v.y = fmaxf(acc[mt][nt][1] + b1, 0.f);
                *reinterpret_cast<float2*>(out + (size_t)ra * D + col) = v;
            }
            int rb = ra + 8;
            if (rb < N_NODES) {
                float2 v;
                v.x = fmaxf(acc[mt][nt][2] + b0, 0.f);
                v.y = fmaxf(acc[mt][nt][3] + b1, 0.f);
                *reinterpret_cast<float2*>(out + (size_t)rb * D + col) = v;
            }
        }
    }
}

// ---------------------------------------------------------------------------
__global__ void k_colstats(const float* __restrict__ h) {
    __shared__ float ssum[D];
    __shared__ float ssq[D];
    int t = threadIdx.x;
    if (t < D) { ssum[t] = 0.f; ssq[t] = 0.f; }
    __syncthreads();

    long long idx = (long long)blockIdx.x * blockDim.x + t;
    long long stride = (long long)gridDim.x * blockDim.x;
    int col = (int)(idx & (D - 1));
    float s = 0.f, q = 0.f;
    for (; idx < (long long)N_NODES * D; idx += stride) {
        float v = h[idx];
        s += v;
        q += v * v;
    }
    atomicAdd(&ssum[col], s);
    atomicAdd(&ssq[col], q);
    __syncthreads();
    if (t < D) {
        atomicAdd(&g_colsum[t], ssum[t]);
        atomicAdd(&g_colsq[t], ssq[t]);
    }
}

__global__ void k_bnprep(const float* __restrict__ gamma,
                         const float* __restrict__ beta) {
    int t = threadIdx.x;
    float inv_n = 1.0f / (float)N_NODES;
    float mu = g_colsum[t] * inv_n;
    float var = g_colsq[t] * inv_n - mu * mu;
    float a = gamma[t] * rsqrtf(var + 1e-5f);
    g_bn[t] = a;
    g_bn[D + t] = beta[t] - mu * a;
}

__global__ void k_bnapply(float* __restrict__ h) {
    int i = blockIdx.x * blockDim.x + threadIdx.x;
    if (i >= N_NODES * D / 4) return;
    int c = (i * 4) & (D - 1);
    float4 v = reinterpret_cast<float4*>(h)[i];
    v.x = g_bn[c + 0] * v.x + g_bn[D + c + 0];
    v.y = g_bn[c + 1] * v.y + g_bn[D + c + 1];
    v.z = g_bn[c + 2] * v.z + g_bn[D + c + 2];
    v.w = g_bn[c + 3] * v.w + g_bn[D + c + 3];
    reinterpret_cast<float4*>(h)[i] = v;
}

// ---------------------------------------------------------------------------
__global__ void __launch_bounds__(256) k_pairs(const float* __restrict__ h,
                                               const int* __restrict__ pairs,
                                               const float* __restrict__ Wfc,
                                               const float* __restrict__ bfc,
                                               float* __restrict__ out) {
    __shared__ float sW[O_OUT][D];
    __shared__ float sb[O_OUT];
    int t = threadIdx.x;
    for (int i = t; i < O_OUT * D; i += 256) sW[i / D][i % D] = Wfc[i];
    if (t < O_OUT) sb[t] = bfc[t];
    __syncthreads();

    int p = (blockIdx.x * 256 + t) >> 5;
    int lane = t & 31;
    if (p >= P_PAIRS) return;

    int i0 = pairs[2 * p];
    int i1 = pairs[2 * p + 1];
    float4 u = reinterpret_cast<const float4*>(h + (size_t)i0 * D)[lane];
    float4 v = reinterpret_cast<const float4*>(h + (size_t)i1 * D)[lane];
    float4 w = make_float4(u.x * v.x, u.y * v.y, u.z * v.z, u.w * v.w);

    float s[O_OUT];
#pragma unroll
    for (int o = 0; o < O_OUT; o++) {
        s[o] = w.x * sW[o][4 * lane + 0] + w.y * sW[o][4 * lane + 1] +
               w.z * sW[o][4 * lane + 2] + w.w * sW[o][4 * lane + 3];
    }
#pragma unroll
    for (int o = 0; o < O_OUT; o++) {
#pragma unroll
        for (int off = 16; off > 0; off >>= 1)
            s[o] += __shfl_xor_sync(0xffffffffu, s[o], off);
    }
    if (lane == 0) {
#pragma unroll
        for (int o = 0; o < O_OUT; o++) out[(size_t)p * O_OUT + o] = s[o] + sb[o];
    }
}

// ---------------------------------------------------------------------------
extern "C" void kernel_launch(void* const* d_in, const int* in_sizes, int n_in,
                              void* d_out, int out_size) {
    const float* x    = (const float*)d_in[0];
    const float* W1a  = (const float*)d_in[1];
    const float* b1a  = (const float*)d_in[2];
    const float* W2a  = (const float*)d_in[3];
    const float* b2a  = (const float*)d_in[4];
    const float* g0   = (const float*)d_in[5];
    const float* bt0  = (const float*)d_in[6];
    const float* eps0 = (const float*)d_in[7];
    const float* W1b  = (const float*)d_in[8];
    const float* b1b  = (const float*)d_in[9];
    const float* W2b  = (const float*)d_in[10];
    const float* b2b  = (const float*)d_in[11];
    const float* g1   = (const float*)d_in[12];
    const float* bt1  = (const float*)d_in[13];
    const float* eps1 = (const float*)d_in[14];
    const float* Wl   = (const float*)d_in[15];
    const float* bl   = (const float*)d_in[16];
    const float* Wfc  = (const float*)d_in[17];
    const float* bfc  = (const float*)d_in[18];
    const int* esrc   = (const int*)d_in[19];
    const int* edst   = (const int*)d_in[20];
    const int* pairs  = (const int*)d_in[21];
    float* out = (float*)d_out;

    float *t, *h;
    cudaGetSymbolAddress((void**)&t, g_t);
    cudaGetSymbolAddress((void**)&h, g_h);

    cudaFuncSetAttribute(k_gemm_tc<0>, cudaFuncAttributeMaxDynamicSharedMemorySize,
                         GEMM_SMEM_BYTES);
    cudaFuncSetAttribute(k_gemm_tc<1>, cudaFuncAttributeMaxDynamicSharedMemorySize,
                         GEMM_SMEM_BYTES);

    const int ZB = (N_NODES * D / 4 + 255) / 256;
    const int SB = (E_EDGES * 32 + 255) / 256;
    const int GB = (N_NODES + 127) / 128;           // 391
    const int PB = (P_PAIRS * 32) / 256;

    // Layer A
    k_zero<<<ZB, 256>>>();
    k_scatter<<<SB, 256>>>(x, esrc, edst);
    k_gemm_tc<1><<<GB, 256, GEMM_SMEM_BYTES>>>(x, W1a, b1a, t, eps0);
    k_gemm_tc<0><<<GB, 256, GEMM_SMEM_BYTES>>>(t, W2a, b2a, h, nullptr);
    k_colstats<<<2048, 256>>>(h);
    k_bnprep<<<1, 128>>>(g0, bt0);
    k_bnapply<<<ZB, 256>>>(h);

    // Layer B
    k_zero<<<ZB, 256>>>();
    k_scatter<<<SB, 256>>>(h, esrc, edst);
    k_gemm_tc<1><<<GB, 256, GEMM_SMEM_BYTES>>>(h, W1b, b1b, t, eps1);
    k_gemm_tc<0><<<GB, 256, GEMM_SMEM_BYTES>>>(t, W2b, b2b, h, nullptr);
    k_colstats<<<2048, 256>>>(h);
    k_bnprep<<<1, 128>>>(g1, bt1);
    k_bnapply<<<ZB, 256>>>(h);

    // Final linear + pair head
    k_gemm_tc<0><<<GB, 256, GEMM_SMEM_BYTES>>>(h, Wl, bl, t, nullptr);
    k_pairs<<<PB, 256>>>(t, pairs, Wfc, bfc, out);
}

// round 3
// speedup vs baseline: 2.0387x; 1.2421x over previous
#include <cuda_runtime.h>
#include <cuda_bf16.h>
#include <cstdint>

#define N_NODES 50000
#define D 128
#define E_EDGES 600000
#define P_PAIRS 131072
#define O_OUT 7

#define ROW_U32 68                          // padded row: 68 u32 = 136 bf16 = 272 B
#define ARR_U32 (128 * ROW_U32)             // one 128x128 bf16 array
#define ARR_BYTES (ARR_U32 * 4)
#define SMEM_MLP (6 * ARR_BYTES)            // A(hi,lo) W1(hi,lo) W2(hi,lo)
#define SMEM_GL  (4 * ARR_BYTES)            // A(hi,lo) W(hi,lo)

// Scratch
__device__ float g_agg[N_NODES * D];
__device__ float g_t[N_NODES * D];
__device__ float g_h[N_NODES * D];
__device__ float g_colsum[D];
__device__ float g_colsq[D];
__device__ float g_bn[2 * D];                // [0:128) a, [128:256) c
__device__ __nv_bfloat16 g_wh[5 * D * D];    // W1a,W2a,W1b,W2b,Wl (hi)
__device__ __nv_bfloat16 g_wl[5 * D * D];    // (lo)

// ---------------------------------------------------------------------------
__global__ void k_prep_w(const float* __restrict__ w0, const float* __restrict__ w1,
                         const float* __restrict__ w2, const float* __restrict__ w3,
                         const float* __restrict__ w4) {
    int i = blockIdx.x * blockDim.x + threadIdx.x;
    if (i >= 5 * D * D) return;
    const float* srcs[5] = {w0, w1, w2, w3, w4};
    float v = srcs[i >> 14][i & 16383];
    __nv_bfloat16 h = __float2bfloat16(v);
    g_wh[i] = h;
    g_wl[i] = __float2bfloat16(v - __bfloat162float(h));
}

__global__ void k_zero() {
    int i = blockIdx.x * blockDim.x + threadIdx.x;
    if (i < N_NODES * D / 4)
        reinterpret_cast<float4*>(g_agg)[i] = make_float4(0.f, 0.f, 0.f, 0.f);
    if (blockIdx.x == 0 && threadIdx.x < D) {
        g_colsum[threadIdx.x] = 0.f;
        g_colsq[threadIdx.x] = 0.f;
    }
}

// ---------------------------------------------------------------------------
// Edge scatter: agg[dst] += f(h[src]); AFF: f(v) = a*v + c  (folded BN affine)
// ---------------------------------------------------------------------------
template <int AFF>
__global__ void k_scatter(const float* __restrict__ h,
                          const int* __restrict__ src,
                          const int* __restrict__ dst) {
    int e = (blockIdx.x * blockDim.x + threadIdx.x) >> 5;
    int lane = threadIdx.x & 31;
    if (e >= E_EDGES) return;
    int s = src[e];
    int d = dst[e];
    float4 v = reinterpret_cast<const float4*>(h + (size_t)s * D)[lane];
    if (AFF) {
        float4 a = *reinterpret_cast<const float4*>(g_bn + lane * 4);
        float4 c = *reinterpret_cast<const float4*>(g_bn + D + lane * 4);
        v.x = a.x * v.x + c.x;
        v.y = a.y * v.y + c.y;
        v.z = a.z * v.z + c.z;
        v.w = a.w * v.w + c.w;
    }
    float* o = g_agg + (size_t)d * D + lane * 4;
    asm volatile("red.global.add.v4.f32 [%0], {%1,%2,%3,%4};"
                 :: "l"(o), "f"(v.x), "f"(v.y), "f"(v.z), "f"(v.w)
                 : "memory");
}

// ---------------------------------------------------------------------------
// MMA helpers
// ---------------------------------------------------------------------------
__device__ __forceinline__ uint32_t smem_u32(const void* p) {
    return (uint32_t)__cvta_generic_to_shared(p);
}
__device__ __forceinline__ void split2(float a, float b, uint32_t& hi, uint32_t& lo) {
    __nv_bfloat162 h = __floats2bfloat162_rn(a, b);
    float ra = a - __bfloat162float(h.x);
    float rb = b - __bfloat162float(h.y);
    __nv_bfloat162 l = __floats2bfloat162_rn(ra, rb);
    hi = *reinterpret_cast<uint32_t*>(&h);
    lo = *reinterpret_cast<uint32_t*>(&l);
}
__device__ __forceinline__ void ldmx4(uint32_t addr, uint32_t r[4]) {
    asm volatile("ldmatrix.sync.aligned.m8n8.x4.shared.b16 {%0,%1,%2,%3}, [%4];"
                 : "=r"(r[0]), "=r"(r[1]), "=r"(r[2]), "=r"(r[3]) : "r"(addr));
}
__device__ __forceinline__ void mma16816(float c[4], const uint32_t a[4],
                                         uint32_t b0, uint32_t b1) {
    asm volatile(
        "mma.sync.aligned.m16n8k16.row.col.f32.bf16.bf16.f32 "
        "{%0,%1,%2,%3},{%4,%5,%6,%7},{%8,%9},{%0,%1,%2,%3};"
        : "+f"(c[0]), "+f"(c[1]), "+f"(c[2]), "+f"(c[3])
        : "r"(a[0]), "r"(a[1]), "r"(a[2]), "r"(a[3]), "r"(b0), "r"(b1));
}
__device__ __forceinline__ void cpa16(uint32_t dst, const void* src) {
    asm volatile("cp.async.cg.shared.global [%0], [%1], 16;"
                 :: "r"(dst), "l"(src) : "memory");
}

// Fused 3-pass (hi*hi + hi*lo + lo*hi) over all 8 k-steps.
__device__ __forceinline__ void mma_3pass(float acc[2][8][4],
                                          uint32_t Ahi, uint32_t Alo,
                                          uint32_t Bhi, uint32_t Blo,
                                          const uint32_t aoff[2],
                                          const uint32_t boff[4]) {
#pragma unroll
    for (int ks = 0; ks < 8; ks++) {
        uint32_t kb = ks * 32;
        uint32_t ah[2][4], al[2][4], bh[4][4], bl[4][4];
#pragma unroll
        for (int mt = 0; mt < 2; mt++) {
            ldmx4(Ahi + aoff[mt] + kb, ah[mt]);
            ldmx4(Alo + aoff[mt] + kb, al[mt]);
        }
#pragma unroll
        for (int np = 0; np < 4; np++) {
            ldmx4(Bhi + boff[np] + kb, bh[np]);
            ldmx4(Blo + boff[np] + kb, bl[np]);
        }
#pragma unroll
        for (int mt = 0; mt < 2; mt++)
#pragma unroll
            for (int nt = 0; nt < 8; nt++) {
                int np = nt >> 1, o = (nt & 1) * 2;
                mma16816(acc[mt][nt], ah[mt], bh[np][o], bh[np][o + 1]);
                mma16816(acc[mt][nt], ah[mt], bl[np][o], bl[np][o + 1]);
                mma16816(acc[mt][nt], al[mt], bh[np][o], bh[np][o + 1]);
            }
    }
}

// A-stage: read x (+agg, +affine), split to bf16 hi/lo in smem.
template <int COMBINE, int AFF>
__device__ __forceinline__ void stage_A(const float* __restrict__ A, float cA,
                                        int row0, int t,
                                        uint32_t* As_hi, uint32_t* As_lo) {
    int row = t >> 1;
    int j0 = (t & 1) * 16;
    int gr = row0 + row;
    const float4* Ar = reinterpret_cast<const float4*>(A + (size_t)gr * D);
    const float4* Gr = reinterpret_cast<const float4*>(g_agg + (size_t)gr * D);
#pragma unroll 4
    for (int j = 0; j < 16; j++) {
        int f4 = j0 + j;
        float4 v = make_float4(0.f, 0.f, 0.f, 0.f);
        if (gr < N_NODES) {
            v = Ar[f4];
            if (AFF) {
                float4 a = *reinterpret_cast<const float4*>(g_bn + f4 * 4);
                float4 c = *reinterpret_cast<const float4*>(g_bn + D + f4 * 4);
                v.x = a.x * v.x + c.x;
                v.y = a.y * v.y + c.y;
                v.z = a.z * v.z + c.z;
                v.w = a.w * v.w + c.w;
            }
            if (COMBINE) {
                float4 q = Gr[f4];
                v.x = cA * v.x + q.x;
                v.y = cA * v.y + q.y;
                v.z = cA * v.z + q.z;
                v.w = cA * v.w + q.w;
            }
        }
        uint32_t h0, l0, h1, l1;
        split2(v.x, v.y, h0, l0);
        split2(v.z, v.w, h1, l1);
        int o = row * ROW_U32 + f4 * 2;
        *reinterpret_cast<uint2*>(&As_hi[o]) = make_uint2(h0, h1);
        *reinterpret_cast<uint2*>(&As_lo[o]) = make_uint2(l0, l1);
    }
}

// cp.async one pre-split 128x128 bf16 weight array into padded smem.
__device__ __forceinline__ void stage_W(const __nv_bfloat16* __restrict__ w,
                                        uint32_t dst_base, int t) {
#pragma unroll
    for (int it = 0; it < 8; it++) {
        int chunk = t + it * 256;            // 0..2047
        int row = chunk >> 4, j = chunk & 15;
        cpa16(dst_base + row * 272 + j * 16, w + row * D + j * 8);
    }
}

// ---------------------------------------------------------------------------
// Fused GIN MLP: h_out = relu(relu(Acomb @ W1^T + b1) @ W2^T + b2), + colstats
// ---------------------------------------------------------------------------
template <int AFF>
__global__ void __launch_bounds__(256) k_mlp(const float* __restrict__ A,
                                             const float* __restrict__ epsp,
                                             const float* __restrict__ b1,
                                             const float* __restrict__ b2,
                                             const __nv_bfloat16* __restrict__ w1h,
                                             const __nv_bfloat16* __restrict__ w1l,
                                             const __nv_bfloat16* __restrict__ w2h,
                                             const __nv_bfloat16* __restrict__ w2l,
                                             float* __restrict__ out) {
    extern __shared__ uint32_t smem[];
    uint32_t* As_hi = smem;
    uint32_t* As_lo = smem + ARR_U32;
    __shared__ float s_sum[D];
    __shared__ float s_sq[D];

    const int t = threadIdx.x;
    const int row0 = blockIdx.x * 128;
    const float cA = 1.0f + *epsp;

    if (t < D) { s_sum[t] = 0.f; s_sq[t] = 0.f; }

    // stage W (async) then A (sync loads overlap with cp.async)
    const uint32_t W1h = smem_u32(smem + 2 * ARR_U32);
    const uint32_t W1l = smem_u32(smem + 3 * ARR_U32);
    const uint32_t W2h = smem_u32(smem + 4 * ARR_U32);
    const uint32_t W2l = smem_u32(smem + 5 * ARR_U32);
    stage_W(w1h, W1h, t);
    stage_W(w1l, W1l, t);
    stage_W(w2h, W2h, t);
    stage_W(w2l, W2l, t);
    asm volatile("cp.async.commit_group;" ::: "memory");
    stage_A<1, AFF>(A, cA, row0, t, As_hi, As_lo);
    asm volatile("cp.async.wait_group 0;" ::: "memory");
    __syncthreads();

    // fragment offsets
    const int warp = t >> 5, lane = t & 31;
    const int wm = warp >> 1, wn = warp & 1;
    uint32_t aoff[2], boff[4];
#pragma unroll
    for (int mt = 0; mt < 2; mt++) {
        int row = wm * 32 + mt * 16 + ((lane >> 3) & 1) * 8 + (lane & 7);
        aoff[mt] = row * 272 + (lane >> 4) * 16;
    }
#pragma unroll
    for (int np = 0; np < 4; np++) {
        int row = wn * 64 + np * 16 + (lane >> 4) * 8 + (lane & 7);
        boff[np] = row * 272 + ((lane >> 3) & 1) * 16;
    }
    const uint32_t Ahi = smem_u32(As_hi), Alo = smem_u32(As_lo);
    const int g = lane >> 2;
    const int c2 = (lane & 3) * 2;

    float acc[2][8][4];
#pragma unroll
    for (int mt = 0; mt < 2; mt++)
#pragma unroll
        for (int nt = 0; nt < 8; nt++)
#pragma unroll
            for (int i = 0; i < 4; i++) acc[mt][nt][i] = 0.f;

    // ---- GEMM1 ----
    mma_3pass(acc, Ahi, Alo, W1h, W1l, aoff, boff);
    __syncthreads();   // everyone done reading As

    // epilogue1: relu+bias, re-split into As smem
    {
        float bc[16];
#pragma unroll
        for (int nt = 0; nt < 8; nt++) {
            int col = wn * 64 + nt * 8 + c2;
            bc[2 * nt] = __ldg(b1 + col);
            bc[2 * nt + 1] = __ldg(b1 + col + 1);
        }
#pragma unroll
        for (int mt = 0; mt < 2; mt++) {
            int ra = wm * 32 + mt * 16 + g;
            int rb = ra + 8;
#pragma unroll
            for (int nt = 0; nt < 8; nt++) {
                int col = wn * 64 + nt * 8 + c2;
                int o = col >> 1;
                float t0 = fmaxf(acc[mt][nt][0] + bc[2 * nt], 0.f);
                float t1 = fmaxf(acc[mt][nt][1] + bc[2 * nt + 1], 0.f);
                float t2 = fmaxf(acc[mt][nt][2] + bc[2 * nt], 0.f);
                float t3 = fmaxf(acc[mt][nt][3] + bc[2 * nt + 1], 0.f);
                uint32_t hi, lo;
                split2(t0, t1, hi, lo);
                As_hi[ra * ROW_U32 + o] = hi;
                As_lo[ra * ROW_U32 + o] = lo;
                split2(t2, t3, hi, lo);
                As_hi[rb * ROW_U32 + o] = hi;
                As_lo[rb * ROW_U32 + o] = lo;
#pragma unroll
                for (int i = 0; i < 4; i++) acc[mt][nt][i] = 0.f;
            }
        }
    }
    __syncthreads();

    // ---- GEMM2 ----
    mma_3pass(acc, Ahi, Alo, W2h, W2l, aoff, boff);

    // epilogue2: relu+bias, store h, accumulate column stats
    {
        float bc[16];
#pragma unroll
        for (int nt = 0; nt < 8; nt++) {
            int col = wn * 64 + nt * 8 + c2;
            bc[2 * nt] = __ldg(b2 + col);
            bc[2 * nt + 1] = __ldg(b2 + col + 1);
        }
        float sp[8][2], qp[8][2];
#pragma unroll
        for (int nt = 0; nt < 8; nt++) {
            sp[nt][0] = sp[nt][1] = 0.f;
            qp[nt][0] = qp[nt][1] = 0.f;
        }
#pragma unroll
        for (int mt = 0; mt < 2; mt++) {
            int ra = row0 + wm * 32 + mt * 16 + g;
            int rb = ra + 8;
#pragma unroll
            for (int nt = 0; nt < 8; nt++) {
                int col = wn * 64 + nt * 8 + c2;
                float v0 = fmaxf(acc[mt][nt][0] + bc[2 * nt], 0.f);
                float v1 = fmaxf(acc[mt][nt][1] + bc[2 * nt + 1], 0.f);
                float v2 = fmaxf(acc[mt][nt][2] + bc[2 * nt], 0.f);
                float v3 = fmaxf(acc[mt][nt][3] + bc[2 * nt + 1], 0.f);
                if (ra < N_NODES) {
                    *reinterpret_cast<float2*>(out + (size_t)ra * D + col) =
                        make_float2(v0, v1);
                    sp[nt][0] += v0; sp[nt][1] += v1;
                    qp[nt][0] += v0 * v0; qp[nt][1] += v1 * v1;
                }
                if (rb < N_NODES) {
                    *reinterpret_cast<float2*>(out + (size_t)rb * D + col) =
                        make_float2(v2, v3);
                    sp[nt][0] += v2; sp[nt][1] += v3;
                    qp[nt][0] += v2 * v2; qp[nt][1] += v3 * v3;
                }
            }
        }
        // reduce across the 8 row-groups (lanes differing in bits 2..4)
#pragma unroll
        for (int nt = 0; nt < 8; nt++) {
#pragma unroll
            for (int d = 4; d < 32; d <<= 1) {
                sp[nt][0] += __shfl_xor_sync(0xffffffffu, sp[nt][0], d);
                sp[nt][1] += __shfl_xor_sync(0xffffffffu, sp[nt][1], d);
                qp[nt][0] += __shfl_xor_sync(0xffffffffu, qp[nt][0], d);
                qp[nt][1] += __shfl_xor_sync(0xffffffffu, qp[nt][1], d);
            }
        }
        if (g == 0) {
#pragma unroll
            for (int nt = 0; nt < 8; nt++) {
                int col = wn * 64 + nt * 8 + c2;
                atomicAdd(&s_sum[col], sp[nt][0]);
                atomicAdd(&s_sum[col + 1], sp[nt][1]);
                atomicAdd(&s_sq[col], qp[nt][0]);
                atomicAdd(&s_sq[col + 1], qp[nt][1]);
            }
        }
    }
    __syncthreads();
    if (t < D) {
        asm volatile("red.global.add.f32 [%0], %1;" :: "l"(&g_colsum[t]), "f"(s_sum[t]) : "memory");
        asm volatile("red.global.add.f32 [%0], %1;" :: "l"(&g_colsq[t]), "f"(s_sq[t]) : "memory");
    }
}

// ---------------------------------------------------------------------------
// Final linear: t = relu((a*h+c) @ Wl^T + bl)
// ---------------------------------------------------------------------------
__global__ void __launch_bounds__(256) k_gemm_l(const float* __restrict__ A,
                                                const float* __restrict__ bias,
                                                const __nv_bfloat16* __restrict__ wh,
                                                const __nv_bfloat16* __restrict__ wl,
                                                float* __restrict__ out) {
    extern __shared__ uint32_t smem[];
    uint32_t* As_hi = smem;
    uint32_t* As_lo = smem + ARR_U32;

    const int t = threadIdx.x;
    const int row0 = blockIdx.x * 128;

    const uint32_t Wh = smem_u32(smem + 2 * ARR_U32);
    const uint32_t Wl = smem_u32(smem + 3 * ARR_U32);
    stage_W(wh, Wh, t);
    stage_W(wl, Wl, t);
    asm volatile("cp.async.commit_group;" ::: "memory");
    stage_A<0, 1>(A, 1.0f, row0, t, As_hi, As_lo);
    asm volatile("cp.async.wait_group 0;" ::: "memory");
    __syncthreads();

    const int warp = t >> 5, lane = t & 31;
    const int wm = warp >> 1, wn = warp & 1;
    uint32_t aoff[2], boff[4];
#pragma unroll
    for (int mt = 0; mt < 2; mt++) {
        int row = wm * 32 + mt * 16 + ((lane >> 3) & 1) * 8 + (lane & 7);
        aoff[mt] = row * 272 + (lane >> 4) * 16;
    }
#pragma unroll
    for (int np = 0; np < 4; np++) {
        int row = wn * 64 + np * 16 + (lane >> 4) * 8 + (lane & 7);
        boff[np] = row * 272 + ((lane >> 3) & 1) * 16;
    }
    const uint32_t Ahi = smem_u32(As_hi), Alo = smem_u32(As_lo);

    float acc[2][8][4];
#pragma unroll
    for (int mt = 0; mt < 2; mt++)
#pragma unroll
        for (int nt = 0; nt < 8; nt++)
#pragma unroll
            for (int i = 0; i < 4; i++) acc[mt][nt][i] = 0.f;

    mma_3pass(acc, Ahi, Alo, Wh, Wl, aoff, boff);

    const int g = lane >> 2;
    const int c2 = (lane & 3) * 2;
#pragma unroll
    for (int nt = 0; nt < 8; nt++) {
        int col = wn * 64 + nt * 8 + c2;
        float b0 = __ldg(bias + col);
        float b1 = __ldg(bias + col + 1);
#pragma unroll
        for (int mt = 0; mt < 2; mt++) {
            int ra = row0 + wm * 32 + mt * 16 + g;
            if (ra < N_NODES)
                *reinterpret_cast<float2*>(out + (size_t)ra * D + col) =
                    make_float2(fmaxf(acc[mt][nt][0] + b0, 0.f),
                                fmaxf(acc[mt][nt][1] + b1, 0.f));
            int rb = ra + 8;
            if (rb < N_NODES)
                *reinterpret_cast<float2*>(out + (size_t)rb * D + col) =
                    make_float2(fmaxf(acc[mt][nt][2] + b0, 0.f),
                                fmaxf(acc[mt][nt][3] + b1, 0.f));
        }
    }
}

// ---------------------------------------------------------------------------
__global__ void k_bnprep(const float* __restrict__ gamma,
                         const float* __restrict__ beta) {
    int t = threadIdx.x;
    float inv_n = 1.0f / (float)N_NODES;
    float mu = g_colsum[t] * inv_n;
    float var = g_colsq[t] * inv_n - mu * mu;
    float a = gamma[t] * rsqrtf(var + 1e-5f);
    g_bn[t] = a;
    g_bn[D + t] = beta[t] - mu * a;
}

// ---------------------------------------------------------------------------
__global__ void __launch_bounds__(256) k_pairs(const float* __restrict__ h,
                                               const int* __restrict__ pairs,
                                               const float* __restrict__ Wfc,
                                               const float* __restrict__ bfc,
                                               float* __restrict__ out) {
    __shared__ float sW[O_OUT][D];
    __shared__ float sb[O_OUT];
    int t = threadIdx.x;
    for (int i = t; i < O_OUT * D; i += 256) sW[i / D][i % D] = Wfc[i];
    if (t < O_OUT) sb[t] = bfc[t];
    __syncthreads();

    int p = (blockIdx.x * 256 + t) >> 5;
    int lane = t & 31;
    if (p >= P_PAIRS) return;

    int i0 = pairs[2 * p];
    int i1 = pairs[2 * p + 1];
    float4 u = reinterpret_cast<const float4*>(h + (size_t)i0 * D)[lane];
    float4 v = reinterpret_cast<const float4*>(h + (size_t)i1 * D)[lane];
    float4 w = make_float4(u.x * v.x, u.y * v.y, u.z * v.z, u.w * v.w);

    float s[O_OUT];
#pragma unroll
    for (int o = 0; o < O_OUT; o++)
        s[o] = w.x * sW[o][4 * lane + 0] + w.y * sW[o][4 * lane + 1] +
               w.z * sW[o][4 * lane + 2] + w.w * sW[o][4 * lane + 3];
#pragma unroll
    for (int o = 0; o < O_OUT; o++)
#pragma unroll
        for (int off = 16; off > 0; off >>= 1)
            s[o] += __shfl_xor_sync(0xffffffffu, s[o], off);
    if (lane == 0)
#pragma unroll
        for (int o = 0; o < O_OUT; o++) out[(size_t)p * O_OUT + o] = s[o] + sb[o];
}

// ---------------------------------------------------------------------------
extern "C" void kernel_launch(void* const* d_in, const int* in_sizes, int n_in,
                              void* d_out, int out_size) {
    const float* x    = (const float*)d_in[0];
    const float* W1a  = (const float*)d_in[1];
    const float* b1a  = (const float*)d_in[2];
    const float* W2a  = (const float*)d_in[3];
    const float* b2a  = (const float*)d_in[4];
    const float* g0   = (const float*)d_in[5];
    const float* bt0  = (const float*)d_in[6];
    const float* eps0 = (const float*)d_in[7];
    const float* W1b  = (const float*)d_in[8];
    const float* b1b  = (const float*)d_in[9];
    const float* W2b  = (const float*)d_in[10];
    const float* b2b  = (const float*)d_in[11];
    const float* g1   = (const float*)d_in[12];
    const float* bt1  = (const float*)d_in[13];
    const float* eps1 = (const float*)d_in[14];
    const float* Wl   = (const float*)d_in[15];
    const float* bl   = (const float*)d_in[16];
    const float* Wfc  = (const float*)d_in[17];
    const float* bfc  = (const float*)d_in[18];
    const int* esrc   = (const int*)d_in[19];
    const int* edst   = (const int*)d_in[20];
    const int* pairs  = (const int*)d_in[21];
    float* out = (float*)d_out;

    float *t, *h;
    __nv_bfloat16 *wh, *wl;
    cudaGetSymbolAddress((void**)&t, g_t);
    cudaGetSymbolAddress((void**)&h, g_h);
    cudaGetSymbolAddress((void**)&wh, g_wh);
    cudaGetSymbolAddress((void**)&wl, g_wl);

    static bool attr_done = false;
    if (!attr_done) {
        cudaFuncSetAttribute(k_mlp<0>, cudaFuncAttributeMaxDynamicSharedMemorySize, SMEM_MLP);
        cudaFuncSetAttribute(k_mlp<1>, cudaFuncAttributeMaxDynamicSharedMemorySize, SMEM_MLP);
        cudaFuncSetAttribute(k_gemm_l, cudaFuncAttributeMaxDynamicSharedMemorySize, SMEM_GL);
        attr_done = true;
    }

    const int ZB = (N_NODES * D / 4 + 255) / 256;
    const int SB = (E_EDGES * 32 + 255) / 256;
    const int GB = (N_NODES + 127) / 128;           // 391
    const int PB = (P_PAIRS * 32) / 256;
    const int WS = D * D;                           // 16384

    k_prep_w<<<(5 * WS + 255) / 256, 256>>>(W1a, W2a, W1b, W2b, Wl);

    // Layer A
    k_zero<<<ZB, 256>>>();
    k_scatter<0><<<SB, 256>>>(x, esrc, edst);
    k_mlp<0><<<GB, 256, SMEM_MLP>>>(x, eps0, b1a, b2a,
                                    wh + 0 * WS, wl + 0 * WS,
                                    wh + 1 * WS, wl + 1 * WS, h);
    k_bnprep<<<1, 128>>>(g0, bt0);

    // Layer B (BN-A affine folded into scatter + mlp stage)
    k_zero<<<ZB, 256>>>();
    k_scatter<1><<<SB, 256>>>(h, esrc, edst);
    k_mlp<1><<<GB, 256, SMEM_MLP>>>(h, eps1, b1b, b2b,
                                    wh + 2 * WS, wl + 2 * WS,
                                    wh + 3 * WS, wl + 3 * WS, h);
    k_bnprep<<<1, 128>>>(g1, bt1);

    // Final linear (BN-B affine folded) + pair head
    k_gemm_l<<<GB, 256, SMEM_GL>>>(h, bl, wh + 4 * WS, wl + 4 * WS, t);
    k_pairs<<<PB, 256>>>(t, pairs, Wfc, bfc, out);
}

// round 5
// speedup vs baseline: 2.0498x; 1.0055x over previous
#include <cuda_runtime.h>
#include <cuda_bf16.h>
#include <cstdint>

#define N_NODES 50000
#define D 128
#define E_EDGES 600000
#define P_PAIRS 131072
#define O_OUT 7
#define NT_TILES 391                         // ceil(N/128)

#define ROW_U32 68                           // padded row: 68 u32 = 272 B
#define ARR_U32 (128 * ROW_U32)
#define ARR_BYTES (ARR_U32 * 4)
#define SMEM_MLP (6 * ARR_BYTES)             // A(hi,lo) W1(hi,lo) W2(hi,lo)
#define SMEM_GL  (4 * ARR_BYTES)

// Scratch
__device__ float g_agg[N_NODES * D];
__device__ float g_t[N_NODES * D];
__device__ float g_h[N_NODES * D];
__device__ float g_colsum[D];
__device__ float g_colsq[D];
__device__ float g_bn[2 * D];                // [0:128) a, [128:256) c
__device__ __nv_bfloat16 g_wh[5 * D * D];    // dense pre-split weights (hi)
__device__ __nv_bfloat16 g_wl[5 * D * D];    // (lo)

// ---------------------------------------------------------------------------
__global__ void k_prep_w(const float* __restrict__ w0, const float* __restrict__ w1,
                         const float* __restrict__ w2, const float* __restrict__ w3,
                         const float* __restrict__ w4) {
    int i = blockIdx.x * blockDim.x + threadIdx.x;
    if (i >= 5 * D * D) return;
    const float* srcs[5] = {w0, w1, w2, w3, w4};
    float v = srcs[i >> 14][i & 16383];
    __nv_bfloat16 h = __float2bfloat16(v);
    g_wh[i] = h;
    g_wl[i] = __float2bfloat16(v - __bfloat162float(h));
}

__global__ void k_zero() {
    int i = blockIdx.x * blockDim.x + threadIdx.x;
    if (i < N_NODES * D / 4)
        reinterpret_cast<float4*>(g_agg)[i] = make_float4(0.f, 0.f, 0.f, 0.f);
    if (blockIdx.x == 0 && threadIdx.x < D) {
        g_colsum[threadIdx.x] = 0.f;
        g_colsq[threadIdx.x] = 0.f;
    }
}

// ---------------------------------------------------------------------------
// Edge scatter: agg[dst] += f(h[src]); AFF folds BN affine
// ---------------------------------------------------------------------------
template <int AFF>
__global__ void k_scatter(const float* __restrict__ h,
                          const int* __restrict__ src,
                          const int* __restrict__ dst) {
    int e = (blockIdx.x * blockDim.x + threadIdx.x) >> 5;
    int lane = threadIdx.x & 31;
    if (e >= E_EDGES) return;
    int s = src[e];
    int d = dst[e];
    float4 v = reinterpret_cast<const float4*>(h + (size_t)s * D)[lane];
    if (AFF) {
        float4 a = *reinterpret_cast<const float4*>(g_bn + lane * 4);
        float4 c = *reinterpret_cast<const float4*>(g_bn + D + lane * 4);
        v.x = a.x * v.x + c.x;
        v.y = a.y * v.y + c.y;
        v.z = a.z * v.z + c.z;
        v.w = a.w * v.w + c.w;
    }
    float* o = g_agg + (size_t)d * D + lane * 4;
    asm volatile("red.global.add.v4.f32 [%0], {%1,%2,%3,%4};"
                 :: "l"(o), "f"(v.x), "f"(v.y), "f"(v.z), "f"(v.w) : "memory");
}

// ---------------------------------------------------------------------------
// MMA helpers (sm_80-baseline instructions only)
// ---------------------------------------------------------------------------
static __device__ __forceinline__ uint32_t smem_u32(const void* p) {
    return (uint32_t)__cvta_generic_to_shared(p);
}
static __device__ __forceinline__ void split2(float a, float b, uint32_t& hi, uint32_t& lo) {
    __nv_bfloat162 h = __floats2bfloat162_rn(a, b);
    float ra = a - __bfloat162float(h.x);
    float rb = b - __bfloat162float(h.y);
    __nv_bfloat162 l = __floats2bfloat162_rn(ra, rb);
    hi = *reinterpret_cast<uint32_t*>(&h);
    lo = *reinterpret_cast<uint32_t*>(&l);
}
static __device__ __forceinline__ void ldmx4(uint32_t addr, uint32_t r[4]) {
    asm volatile("ldmatrix.sync.aligned.m8n8.x4.shared.b16 {%0,%1,%2,%3}, [%4];"
                 : "=r"(r[0]), "=r"(r[1]), "=r"(r[2]), "=r"(r[3]) : "r"(addr));
}
static __device__ __forceinline__ void mma16816(float c[4], const uint32_t a[4],
                                                uint32_t b0, uint32_t b1) {
    asm volatile(
        "mma.sync.aligned.m16n8k16.row.col.f32.bf16.bf16.f32 "
        "{%0,%1,%2,%3},{%4,%5,%6,%7},{%8,%9},{%0,%1,%2,%3};"
        : "+f"(c[0]), "+f"(c[1]), "+f"(c[2]), "+f"(c[3])
        : "r"(a[0]), "r"(a[1]), "r"(a[2]), "r"(a[3]), "r"(b0), "r"(b1));
}
static __device__ __forceinline__ void cpa16(uint32_t dst, const void* src) {
    asm volatile("cp.async.cg.shared.global [%0], [%1], 16;"
                 :: "r"(dst), "l"(src) : "memory");
}

// 16-warp fused 3-pass GEMM body (warp tile 32 rows x 32 cols)
static __device__ __forceinline__ void mma_3pass(float acc[2][4][4],
                                                 uint32_t Ahi, uint32_t Alo,
                                                 uint32_t Bhi, uint32_t Blo,
                                                 const uint32_t aoff[2],
                                                 const uint32_t boff[2]) {
#pragma unroll
    for (int ks = 0; ks < 8; ks++) {
        uint32_t kb = ks * 32;
        uint32_t ah[2][4], al[2][4], bh[2][4], bl[2][4];
#pragma unroll
        for (int mt = 0; mt < 2; mt++) {
            ldmx4(Ahi + aoff[mt] + kb, ah[mt]);
            ldmx4(Alo + aoff[mt] + kb, al[mt]);
        }
#pragma unroll
        for (int np = 0; np < 2; np++) {
            ldmx4(Bhi + boff[np] + kb, bh[np]);
            ldmx4(Blo + boff[np] + kb, bl[np]);
        }
#pragma unroll
        for (int mt = 0; mt < 2; mt++)
#pragma unroll
            for (int nt = 0; nt < 4; nt++) {
                int np = nt >> 1, o = (nt & 1) * 2;
                mma16816(acc[mt][nt], ah[mt], bh[np][o], bh[np][o + 1]);
                mma16816(acc[mt][nt], ah[mt], bl[np][o], bl[np][o + 1]);
                mma16816(acc[mt][nt], al[mt], bh[np][o], bh[np][o + 1]);
            }
    }
}

// A-stage for 512 threads: read (+agg, +affine), split to bf16 hi/lo smem
template <int COMBINE, int AFF>
static __device__ __forceinline__ void stage_A(const float* __restrict__ A, float cA,
                                               int row0, int t,
                                               uint32_t* As_hi, uint32_t* As_lo) {
    int row = t >> 2, q = t & 3, gr = row0 + row;
    const float4* Ar = reinterpret_cast<const float4*>(A + (size_t)gr * D);
    const float4* Gr = reinterpret_cast<const float4*>(g_agg + (size_t)gr * D);
#pragma unroll
    for (int j = 0; j < 8; j++) {
        int f4 = q * 8 + j;
        float4 v = make_float4(0.f, 0.f, 0.f, 0.f);
        if (gr < N_NODES) {
            v = Ar[f4];
            if (AFF) {
                float4 a = *reinterpret_cast<const float4*>(g_bn + f4 * 4);
                float4 c = *reinterpret_cast<const float4*>(g_bn + D + f4 * 4);
                v.x = a.x * v.x + c.x;
                v.y = a.y * v.y + c.y;
                v.z = a.z * v.z + c.z;
                v.w = a.w * v.w + c.w;
            }
            if (COMBINE) {
                float4 q4 = Gr[f4];
                v.x = cA * v.x + q4.x;
                v.y = cA * v.y + q4.y;
                v.z = cA * v.z + q4.z;
                v.w = cA * v.w + q4.w;
            }
        }
        uint32_t h0, l0, h1, l1;
        split2(v.x, v.y, h0, l0);
        split2(v.z, v.w, h1, l1);
        int o = row * ROW_U32 + f4 * 2;
        *reinterpret_cast<uint2*>(&As_hi[o]) = make_uint2(h0, h1);
        *reinterpret_cast<uint2*>(&As_lo[o]) = make_uint2(l0, l1);
    }
}

// cp.async one dense 128x128 bf16 weight array into padded smem (512 thr)
static __device__ __forceinline__ void stage_W(const __nv_bfloat16* __restrict__ w,
                                               uint32_t dbase, int t) {
#pragma unroll
    for (int it = 0; it < 4; it++) {
        int c = t + it * 512;                 // 0..2047
        int row = c >> 4, j = c & 15;
        cpa16(dbase + row * 272 + j * 16, w + row * D + j * 8);
    }
}

// ---------------------------------------------------------------------------
// Persistent fused GIN MLP (512 threads, 16 warps):
//   h = relu(relu(Acomb @ W1^T + b1) @ W2^T + b2), + column stats
// ---------------------------------------------------------------------------
template <int AFF>
__global__ void __launch_bounds__(512) k_mlp(const float* __restrict__ A,
                                             const float* __restrict__ epsp,
                                             const float* __restrict__ b1,
                                             const float* __restrict__ b2,
                                             const __nv_bfloat16* __restrict__ w1h,
                                             const __nv_bfloat16* __restrict__ w1l,
                                             const __nv_bfloat16* __restrict__ w2h,
                                             const __nv_bfloat16* __restrict__ w2l,
                                             float* __restrict__ out) {
    extern __shared__ uint32_t smem[];
    uint32_t* As_hi = smem;
    uint32_t* As_lo = smem + ARR_U32;
    __shared__ float sb1[D], sb2[D], s_sum[D], s_sq[D];

    const int t = threadIdx.x, warp = t >> 5, lane = t & 31;
    const int wm = warp & 3, wn = warp >> 2;
    const float cA = 1.0f + *epsp;

    if (t < D) {
        sb1[t] = __ldg(b1 + t);
        sb2[t] = __ldg(b2 + t);
        s_sum[t] = 0.f;
        s_sq[t] = 0.f;
    }

    const uint32_t W1h = smem_u32(smem + 2 * ARR_U32);
    const uint32_t W1l = smem_u32(smem + 3 * ARR_U32);
    const uint32_t W2h = smem_u32(smem + 4 * ARR_U32);
    const uint32_t W2l = smem_u32(smem + 5 * ARR_U32);
    stage_W(w1h, W1h, t);
    stage_W(w1l, W1l, t);
    stage_W(w2h, W2h, t);
    stage_W(w2l, W2l, t);
    asm volatile("cp.async.commit_group;" ::: "memory");

    // fragment offsets
    uint32_t aoff[2], boff[2];
#pragma unroll
    for (int mt = 0; mt < 2; mt++) {
        int row = wm * 32 + mt * 16 + ((lane >> 3) & 1) * 8 + (lane & 7);
        aoff[mt] = row * 272 + (lane >> 4) * 16;
    }
#pragma unroll
    for (int np = 0; np < 2; np++) {
        int row = wn * 32 + np * 16 + (lane >> 4) * 8 + (lane & 7);
        boff[np] = row * 272 + ((lane >> 3) & 1) * 16;
    }
    const uint32_t Ahi = smem_u32(As_hi), Alo = smem_u32(As_lo);
    const int g = lane >> 2;
    const int c2 = (lane & 3) * 2;

    for (int tile = blockIdx.x; tile < NT_TILES; tile += gridDim.x) {
        const int row0 = tile * 128;
        stage_A<1, AFF>(A, cA, row0, t, As_hi, As_lo);
        asm volatile("cp.async.wait_group 0;" ::: "memory");
        __syncthreads();

        float acc[2][4][4];
#pragma unroll
        for (int mt = 0; mt < 2; mt++)
#pragma unroll
            for (int nt = 0; nt < 4; nt++)
#pragma unroll
                for (int i = 0; i < 4; i++) acc[mt][nt][i] = 0.f;

        // ---- GEMM1 ----
        mma_3pass(acc, Ahi, Alo, W1h, W1l, aoff, boff);
        __syncthreads();   // everyone done reading As

        // epilogue1: relu+bias, re-split into As smem
#pragma unroll
        for (int mt = 0; mt < 2; mt++) {
            int ra = wm * 32 + mt * 16 + g;
            int rb = ra + 8;
#pragma unroll
            for (int nt = 0; nt < 4; nt++) {
                int col = wn * 32 + nt * 8 + c2;
                int o = col >> 1;
                float t0 = fmaxf(acc[mt][nt][0] + sb1[col], 0.f);
                float t1 = fmaxf(acc[mt][nt][1] + sb1[col + 1], 0.f);
                float t2 = fmaxf(acc[mt][nt][2] + sb1[col], 0.f);
                float t3 = fmaxf(acc[mt][nt][3] + sb1[col + 1], 0.f);
                uint32_t hi, lo;
                split2(t0, t1, hi, lo);
                As_hi[ra * ROW_U32 + o] = hi;
                As_lo[ra * ROW_U32 + o] = lo;
                split2(t2, t3, hi, lo);
                As_hi[rb * ROW_U32 + o] = hi;
                As_lo[rb * ROW_U32 + o] = lo;
#pragma unroll
                for (int i = 0; i < 4; i++) acc[mt][nt][i] = 0.f;
            }
        }
        __syncthreads();

        // ---- GEMM2 ----
        mma_3pass(acc, Ahi, Alo, W2h, W2l, aoff, boff);

        // epilogue2: relu+bias, store h, accumulate column stats
        {
            float sp[4][2], qp[4][2];
#pragma unroll
            for (int nt = 0; nt < 4; nt++) {
                sp[nt][0] = sp[nt][1] = 0.f;
                qp[nt][0] = qp[nt][1] = 0.f;
            }
#pragma unroll
            for (int mt = 0; mt < 2; mt++) {
                int ra = row0 + wm * 32 + mt * 16 + g;
                int rb = ra + 8;
#pragma unroll
                for (int nt = 0; nt < 4; nt++) {
                    int col = wn * 32 + nt * 8 + c2;
                    float v0 = fmaxf(acc[mt][nt][0] + sb2[col], 0.f);
                    float v1 = fmaxf(acc[mt][nt][1] + sb2[col + 1], 0.f);
                    float v2 = fmaxf(acc[mt][nt][2] + sb2[col], 0.f);
                    float v3 = fmaxf(acc[mt][nt][3] + sb2[col + 1], 0.f);
                    if (ra < N_NODES) {
                        *reinterpret_cast<float2*>(out + (size_t)ra * D + col) =
                            make_float2(v0, v1);
                        sp[nt][0] += v0; sp[nt][1] += v1;
                        qp[nt][0] += v0 * v0; qp[nt][1] += v1 * v1;
                    }
                    if (rb < N_NODES) {
                        *reinterpret_cast<float2*>(out + (size_t)rb * D + col) =
                            make_float2(v2, v3);
                        sp[nt][0] += v2; sp[nt][1] += v3;
                        qp[nt][0] += v2 * v2; qp[nt][1] += v3 * v3;
                    }
                }
            }
#pragma unroll
            for (int nt = 0; nt < 4; nt++) {
#pragma unroll
                for (int d = 4; d < 32; d <<= 1) {
                    sp[nt][0] += __shfl_xor_sync(0xffffffffu, sp[nt][0], d);
                    sp[nt][1] += __shfl_xor_sync(0xffffffffu, sp[nt][1], d);
                    qp[nt][0] += __shfl_xor_sync(0xffffffffu, qp[nt][0], d);
                    qp[nt][1] += __shfl_xor_sync(0xffffffffu, qp[nt][1], d);
                }
            }
            if (g == 0) {
#pragma unroll
                for (int nt = 0; nt < 4; nt++) {
                    int col = wn * 32 + nt * 8 + c2;
                    atomicAdd(&s_sum[col], sp[nt][0]);
                    atomicAdd(&s_sum[col + 1], sp[nt][1]);
                    atomicAdd(&s_sq[col], qp[nt][0]);
                    atomicAdd(&s_sq[col + 1], qp[nt][1]);
                }
            }
        }
        __syncthreads();   // As reuse + s_sum ordering for next tile
    }

    if (t < D) {
        asm volatile("red.global.add.f32 [%0], %1;" :: "l"(&g_colsum[t]), "f"(s_sum[t]) : "memory");
        asm volatile("red.global.add.f32 [%0], %1;" :: "l"(&g_colsq[t]), "f"(s_sq[t]) : "memory");
    }
}

// ---------------------------------------------------------------------------
// Persistent final linear (512 threads): t = relu((a*h+c) @ Wl^T + bl)
// ---------------------------------------------------------------------------
__global__ void __launch_bounds__(512) k_gemm_l(const float* __restrict__ A,
                                                const float* __restrict__ bias,
                                                const __nv_bfloat16* __restrict__ wh,
                                                const __nv_bfloat16* __restrict__ wl,
                                                float* __restrict__ out) {
    extern __shared__ uint32_t smem[];
    uint32_t* As_hi = smem;
    uint32_t* As_lo = smem + ARR_U32;
    __shared__ float sb[D];

    const int t = threadIdx.x, warp = t >> 5, lane = t & 31;
    const int wm = warp & 3, wn = warp >> 2;

    if (t < D) sb[t] = __ldg(bias + t);

    const uint32_t Wh = smem_u32(smem + 2 * ARR_U32);
    const uint32_t Wl = smem_u32(smem + 3 * ARR_U32);
    stage_W(wh, Wh, t);
    stage_W(wl, Wl, t);
    asm volatile("cp.async.commit_group;" ::: "memory");

    uint32_t aoff[2], boff[2];
#pragma unroll
    for (int mt = 0; mt < 2; mt++) {
        int row = wm * 32 + mt * 16 + ((lane >> 3) & 1) * 8 + (lane & 7);
        aoff[mt] = row * 272 + (lane >> 4) * 16;
    }
#pragma unroll
    for (int np = 0; np < 2; np++) {
        int row = wn * 32 + np * 16 + (lane >> 4) * 8 + (lane & 7);
        boff[np] = row * 272 + ((lane >> 3) & 1) * 16;
    }
    const uint32_t Ahi = smem_u32(As_hi), Alo = smem_u32(As_lo);
    const int g = lane >> 2;
    const int c2 = (lane & 3) * 2;

    for (int tile = blockIdx.x; tile < NT_TILES; tile += gridDim.x) {
        const int row0 = tile * 128;
        stage_A<0, 1>(A, 1.0f, row0, t, As_hi, As_lo);
        asm volatile("cp.async.wait_group 0;" ::: "memory");
        __syncthreads();

        float acc[2][4][4];
#pragma unroll
        for (int mt = 0; mt < 2; mt++)
#pragma unroll
            for (int nt = 0; nt < 4; nt++)
#pragma unroll
                for (int i = 0; i < 4; i++) acc[mt][nt][i] = 0.f;

        mma_3pass(acc, Ahi, Alo, Wh, Wl, aoff, boff);

#pragma unroll
        for (int mt = 0; mt < 2; mt++) {
            int ra = row0 + wm * 32 + mt * 16 + g;
            int rb = ra + 8;
#pragma unroll
            for (int nt = 0; nt < 4; nt++) {
                int col = wn * 32 + nt * 8 + c2;
                if (ra < N_NODES)
                    *reinterpret_cast<float2*>(out + (size_t)ra * D + col) =
                        make_float2(fmaxf(acc[mt][nt][0] + sb[col], 0.f),
                                    fmaxf(acc[mt][nt][1] + sb[col + 1], 0.f));
                if (rb < N_NODES)
                    *reinterpret_cast<float2*>(out + (size_t)rb * D + col) =
                        make_float2(fmaxf(acc[mt][nt][2] + sb[col], 0.f),
                                    fmaxf(acc[mt][nt][3] + sb[col + 1], 0.f));
            }
        }
        __syncthreads();   // As reuse next tile
    }
}

// ---------------------------------------------------------------------------
__global__ void k_bnprep(const float* __restrict__ gamma,
                         const float* __restrict__ beta) {
    int t = threadIdx.x;
    float inv_n = 1.0f / (float)N_NODES;
    float mu = g_colsum[t] * inv_n;
    float var = g_colsq[t] * inv_n - mu * mu;
    float a = gamma[t] * rsqrtf(var + 1e-5f);
    g_bn[t] = a;
    g_bn[D + t] = beta[t] - mu * a;
}

// ---------------------------------------------------------------------------
__global__ void __launch_bounds__(256) k_pairs(const float* __restrict__ h,
                                               const int* __restrict__ pairs,
                                               const float* __restrict__ Wfc,
                                               const float* __restrict__ bfc,
                                               float* __restrict__ out) {
    __shared__ float sW[O_OUT][D];
    __shared__ float sb[O_OUT];
    int t = threadIdx.x;
    for (int i = t; i < O_OUT * D; i += 256) sW[i / D][i % D] = Wfc[i];
    if (t < O_OUT) sb[t] = bfc[t];
    __syncthreads();

    int p = (blockIdx.x * 256 + t) >> 5;
    int lane = t & 31;
    if (p >= P_PAIRS) return;

    int i0 = pairs[2 * p];
    int i1 = pairs[2 * p + 1];
    float4 u = reinterpret_cast<const float4*>(h + (size_t)i0 * D)[lane];
    float4 v = reinterpret_cast<const float4*>(h + (size_t)i1 * D)[lane];
    float4 w = make_float4(u.x * v.x, u.y * v.y, u.z * v.z, u.w * v.w);

    float s[O_OUT];
#pragma unroll
    for (int o = 0; o < O_OUT; o++)
        s[o] = w.x * sW[o][4 * lane + 0] + w.y * sW[o][4 * lane + 1] +
               w.z * sW[o][4 * lane + 2] + w.w * sW[o][4 * lane + 3];
#pragma unroll
    for (int o = 0; o < O_OUT; o++)
#pragma unroll
        for (int off = 16; off > 0; off >>= 1)
            s[o] += __shfl_xor_sync(0xffffffffu, s[o], off);
    if (lane == 0)
#pragma unroll
        for (int o = 0; o < O_OUT; o++) out[(size_t)p * O_OUT + o] = s[o] + sb[o];
}

// ---------------------------------------------------------------------------
extern "C" void kernel_launch(void* const* d_in, const int* in_sizes, int n_in,
                              void* d_out, int out_size) {
    const float* x    = (const float*)d_in[0];
    const float* W1a  = (const float*)d_in[1];
    const float* b1a  = (const float*)d_in[2];
    const float* W2a  = (const float*)d_in[3];
    const float* b2a  = (const float*)d_in[4];
    const float* g0   = (const float*)d_in[5];
    const float* bt0  = (const float*)d_in[6];
    const float* eps0 = (const float*)d_in[7];
    const float* W1b  = (const float*)d_in[8];
    const float* b1b  = (const float*)d_in[9];
    const float* W2b  = (const float*)d_in[10];
    const float* b2b  = (const float*)d_in[11];
    const float* g1   = (const float*)d_in[12];
    const float* bt1  = (const float*)d_in[13];
    const float* eps1 = (const float*)d_in[14];
    const float* Wl   = (const float*)d_in[15];
    const float* bl   = (const float*)d_in[16];
    const float* Wfc  = (const float*)d_in[17];
    const float* bfc  = (const float*)d_in[18];
    const int* esrc   = (const int*)d_in[19];
    const int* edst   = (const int*)d_in[20];
    const int* pairs  = (const int*)d_in[21];
    float* out = (float*)d_out;

    float *t, *h;
    __nv_bfloat16 *wh, *wl;
    cudaGetSymbolAddress((void**)&t, g_t);
    cudaGetSymbolAddress((void**)&h, g_h);
    cudaGetSymbolAddress((void**)&wh, g_wh);
    cudaGetSymbolAddress((void**)&wl, g_wl);

    cudaFuncSetAttribute(k_mlp<0>, cudaFuncAttributeMaxDynamicSharedMemorySize, SMEM_MLP);
    cudaFuncSetAttribute(k_mlp<1>, cudaFuncAttributeMaxDynamicSharedMemorySize, SMEM_MLP);
    cudaFuncSetAttribute(k_gemm_l, cudaFuncAttributeMaxDynamicSharedMemorySize, SMEM_GL);

    const int ZB = (N_NODES * D / 4 + 255) / 256;
    const int SB = (E_EDGES * 32 + 255) / 256;
    const int PB = (P_PAIRS * 32) / 256;
    const int WS = D * D;
    const int PG = 148;                       // persistent grid

    k_prep_w<<<(5 * WS + 255) / 256, 256>>>(W1a, W2a, W1b, W2b, Wl);

    // Layer A
    k_zero<<<ZB, 256>>>();
    k_scatter<0><<<SB, 256>>>(x, esrc, edst);
    k_mlp<0><<<PG, 512, SMEM_MLP>>>(x, eps0, b1a, b2a,
                                    wh + 0 * WS, wl + 0 * WS,
                                    wh + 1 * WS, wl + 1 * WS, h);
    k_bnprep<<<1, 128>>>(g0, bt0);

    // Layer B (BN-A affine folded into scatter + mlp stage)
    k_zero<<<ZB, 256>>>();
    k_scatter<1><<<SB, 256>>>(h, esrc, edst);
    k_mlp<1><<<PG, 512, SMEM_MLP>>>(h, eps1, b1b, b2b,
                                    wh + 2 * WS, wl + 2 * WS,
                                    wh + 3 * WS, wl + 3 * WS, h);
    k_bnprep<<<1, 128>>>(g1, bt1);

    // Final linear (BN-B affine folded) + pair head
    k_gemm_l<<<PG, 512, SMEM_GL>>>(h, bl, wh + 4 * WS, wl + 4 * WS, t);
    k_pairs<<<PB, 256>>>(t, pairs, Wfc, bfc, out);
}

// round 7
// speedup vs baseline: 2.1329x; 1.0406x over previous
#include <cuda_runtime.h>
#include <cuda_bf16.h>
#include <cstdint>

#define N_NODES 50000
#define D 128
#define E_EDGES 600000
#define P_PAIRS 131072
#define O_OUT 7
#define NT_TILES 391                         // ceil(N/128)

#define ROW_U32 68                           // padded row: 68 u32 = 272 B
#define ARR_U32 (128 * ROW_U32)
#define ARR_BYTES (ARR_U32 * 4)
#define SMEM_MLP (6 * ARR_BYTES)             // A(hi,lo) W1(hi,lo) W2(hi,lo)
#define SMEM_GL  (4 * ARR_BYTES)

// Scratch
__device__ float g_agg[N_NODES * D];
__device__ float g_t[N_NODES * D];
__device__ float g_h[N_NODES * D];
__device__ float g_colsum[D];
__device__ float g_colsq[D];
__device__ float g_bn[2 * D];                // [0:128) a, [128:256) c
__device__ __nv_bfloat16 g_wh[5 * D * D];    // dense pre-split weights (hi)
__device__ __nv_bfloat16 g_wl[5 * D * D];    // (lo residual)

// ---------------------------------------------------------------------------
__global__ void k_prep_w(const float* __restrict__ w0, const float* __restrict__ w1,
                         const float* __restrict__ w2, const float* __restrict__ w3,
                         const float* __restrict__ w4) {
    int i = blockIdx.x * blockDim.x + threadIdx.x;
    if (i >= 5 * D * D) return;
    const float* srcs[5] = {w0, w1, w2, w3, w4};
    float v = srcs[i >> 14][i & 16383];
    __nv_bfloat16 h = __float2bfloat16(v);
    g_wh[i] = h;
    g_wl[i] = __float2bfloat16(v - __bfloat162float(h));
}

__global__ void k_zero() {
    int i = blockIdx.x * blockDim.x + threadIdx.x;
    if (i < N_NODES * D / 4)
        reinterpret_cast<float4*>(g_agg)[i] = make_float4(0.f, 0.f, 0.f, 0.f);
    if (blockIdx.x == 0 && threadIdx.x < D) {
        g_colsum[threadIdx.x] = 0.f;
        g_colsq[threadIdx.x] = 0.f;
    }
}

// ---------------------------------------------------------------------------
// Edge scatter: agg[dst] += f(h[src]); AFF folds BN affine
// ---------------------------------------------------------------------------
template <int AFF>
__global__ void k_scatter(const float* __restrict__ h,
                          const int* __restrict__ src,
                          const int* __restrict__ dst) {
    int e = (blockIdx.x * blockDim.x + threadIdx.x) >> 5;
    int lane = threadIdx.x & 31;
    if (e >= E_EDGES) return;
    int s = src[e];
    int d = dst[e];
    float4 v = reinterpret_cast<const float4*>(h + (size_t)s * D)[lane];
    if (AFF) {
        float4 a = *reinterpret_cast<const float4*>(g_bn + lane * 4);
        float4 c = *reinterpret_cast<const float4*>(g_bn + D + lane * 4);
        v.x = a.x * v.x + c.x;
        v.y = a.y * v.y + c.y;
        v.z = a.z * v.z + c.z;
        v.w = a.w * v.w + c.w;
    }
    float* o = g_agg + (size_t)d * D + lane * 4;
    asm volatile("red.global.add.v4.f32 [%0], {%1,%2,%3,%4};"
                 :: "l"(o), "f"(v.x), "f"(v.y), "f"(v.z), "f"(v.w) : "memory");
}

// ---------------------------------------------------------------------------
// MMA helpers
// ---------------------------------------------------------------------------
static __device__ __forceinline__ uint32_t smem_u32(const void* p) {
    return (uint32_t)__cvta_generic_to_shared(p);
}
static __device__ __forceinline__ void split2(float a, float b, uint32_t& hi, uint32_t& lo) {
    __nv_bfloat162 h = __floats2bfloat162_rn(a, b);
    float ra = a - __bfloat162float(h.x);
    float rb = b - __bfloat162float(h.y);
    __nv_bfloat162 l = __floats2bfloat162_rn(ra, rb);
    hi = *reinterpret_cast<uint32_t*>(&h);
    lo = *reinterpret_cast<uint32_t*>(&l);
}
static __device__ __forceinline__ void ldmx4(uint32_t addr, uint32_t r[4]) {
    asm volatile("ldmatrix.sync.aligned.m8n8.x4.shared.b16 {%0,%1,%2,%3}, [%4];"
                 : "=r"(r[0]), "=r"(r[1]), "=r"(r[2]), "=r"(r[3]) : "r"(addr));
}
static __device__ __forceinline__ void mma16816(float c[4], const uint32_t a[4],
                                                uint32_t b0, uint32_t b1) {
    asm volatile(
        "mma.sync.aligned.m16n8k16.row.col.f32.bf16.bf16.f32 "
        "{%0,%1,%2,%3},{%4,%5,%6,%7},{%8,%9},{%0,%1,%2,%3};"
        : "+f"(c[0]), "+f"(c[1]), "+f"(c[2]), "+f"(c[3])
        : "r"(a[0]), "r"(a[1]), "r"(a[2]), "r"(a[3]), "r"(b0), "r"(b1));
}
static __device__ __forceinline__ void cpa16(uint32_t dst, const void* src) {
    asm volatile("cp.async.cg.shared.global [%0], [%1], 16;"
                 :: "r"(dst), "l"(src) : "memory");
}

// 3-pass GEMM body (hi*hi + hi*lo + lo*hi), pass-major MMA order so the
// 3 same-accumulator MMAs are 8 independent MMAs apart.
static __device__ __forceinline__ void mma_3pass(float acc[2][4][4],
                                                 uint32_t Ahi, uint32_t Alo,
                                                 uint32_t Bhi, uint32_t Blo,
                                                 const uint32_t aoff[2],
                                                 const uint32_t boff[2]) {
#pragma unroll
    for (int ks = 0; ks < 8; ks++) {
        uint32_t kb = ks * 32;
        uint32_t ah[2][4], al[2][4], bh[2][4], bl[2][4];
#pragma unroll
        for (int mt = 0; mt < 2; mt++) {
            ldmx4(Ahi + aoff[mt] + kb, ah[mt]);
            ldmx4(Alo + aoff[mt] + kb, al[mt]);
        }
#pragma unroll
        for (int np = 0; np < 2; np++) {
            ldmx4(Bhi + boff[np] + kb, bh[np]);
            ldmx4(Blo + boff[np] + kb, bl[np]);
        }
        // pass 0: hi*hi over all 8 accumulators
#pragma unroll
        for (int mt = 0; mt < 2; mt++)
#pragma unroll
            for (int nt = 0; nt < 4; nt++) {
                int np = nt >> 1, o = (nt & 1) * 2;
                mma16816(acc[mt][nt], ah[mt], bh[np][o], bh[np][o + 1]);
            }
        // pass 1: hi*lo
#pragma unroll
        for (int mt = 0; mt < 2; mt++)
#pragma unroll
            for (int nt = 0; nt < 4; nt++) {
                int np = nt >> 1, o = (nt & 1) * 2;
                mma16816(acc[mt][nt], ah[mt], bl[np][o], bl[np][o + 1]);
            }
        // pass 2: lo*hi
#pragma unroll
        for (int mt = 0; mt < 2; mt++)
#pragma unroll
            for (int nt = 0; nt < 4; nt++) {
                int np = nt >> 1, o = (nt & 1) * 2;
                mma16816(acc[mt][nt], al[mt], bh[np][o], bh[np][o + 1]);
            }
    }
}

// cp.async one dense 128x128 bf16 weight array into padded smem (512 thr)
static __device__ __forceinline__ void stage_W(const __nv_bfloat16* __restrict__ w,
                                               uint32_t dbase, int t) {
#pragma unroll
    for (int it = 0; it < 4; it++) {
        int c = t + it * 512;                 // 0..2047
        int row = c >> 4, j = c & 15;
        cpa16(dbase + row * 272 + j * 16, w + row * D + j * 8);
    }
}

// prefetch one tile's A rows into registers (8 float4 per thread, 512 thr)
static __device__ __forceinline__ void prefetch_A(const float* __restrict__ A,
                                                  int gr, int sq, float4 px[8]) {
    if (gr < N_NODES) {
        const float4* Ar = reinterpret_cast<const float4*>(A + (size_t)gr * D);
#pragma unroll
        for (int j = 0; j < 8; j++) px[j] = Ar[sq * 8 + j];
    }
}

// stage from prefetched regs: (+affine)(+agg), split to bf16 hi/lo smem
template <int COMBINE, int AFF>
static __device__ __forceinline__ void stage_from_regs(const float4 px[8], int gr,
                                                       int srow, int sq,
                                                       uint32_t* As_hi, uint32_t* As_lo) {
    const float4* Gr = reinterpret_cast<const float4*>(g_agg + (size_t)gr * D);
#pragma unroll
    for (int j = 0; j < 8; j++) {
        int f4 = sq * 8 + j;
        float4 v = make_float4(0.f, 0.f, 0.f, 0.f);
        if (gr < N_NODES) {
            v = px[j];
            if (AFF) {
                float4 a = *reinterpret_cast<const float4*>(g_bn + f4 * 4);
                float4 c = *reinterpret_cast<const float4*>(g_bn + D + f4 * 4);
                v.x = a.x * v.x + c.x; v.y = a.y * v.y + c.y;
                v.z = a.z * v.z + c.z; v.w = a.w * v.w + c.w;
            }
            if (COMBINE) {
                float4 q4 = Gr[f4];
                v.x = fmaf(v.x, 1.f, 0.f), v.x = v.x; // keep order
                v.x = v.x * 1.f;
            }
        }
        // (COMBINE handled below to keep cA in caller)
        uint32_t h0, l0, h1, l1;
        split2(v.x, v.y, h0, l0);
        split2(v.z, v.w, h1, l1);
        int o = srow * ROW_U32 + f4 * 2;
        *reinterpret_cast<uint2*>(&As_hi[o]) = make_uint2(h0, h1);
        *reinterpret_cast<uint2*>(&As_lo[o]) = make_uint2(l0, l1);
    }
}

// ---------------------------------------------------------------------------
// Persistent fused GIN MLP (512 threads), bf16 3-pass, A register-prefetch
// ---------------------------------------------------------------------------
template <int AFF>
__global__ void __launch_bounds__(512) k_mlp(const float* __restrict__ A,
                                             const float* __restrict__ epsp,
                                             const float* __restrict__ b1,
                                             const float* __restrict__ b2,
                                             const __nv_bfloat16* __restrict__ w1h,
                                             const __nv_bfloat16* __restrict__ w1l,
                                             const __nv_bfloat16* __restrict__ w2h,
                                             const __nv_bfloat16* __restrict__ w2l,
                                             float* __restrict__ out) {
    extern __shared__ uint32_t smem[];
    uint32_t* As_hi = smem;
    uint32_t* As_lo = smem + ARR_U32;
    __shared__ float sb1[D], sb2[D], s_sum[D], s_sq[D];

    const int t = threadIdx.x, warp = t >> 5, lane = t & 31;
    const int wm = warp & 3, wn = warp >> 2;
    const float cA = 1.0f + *epsp;

    if (t < D) {
        sb1[t] = __ldg(b1 + t);
        sb2[t] = __ldg(b2 + t);
        s_sum[t] = 0.f;
        s_sq[t] = 0.f;
    }

    const uint32_t W1h = smem_u32(smem + 2 * ARR_U32);
    const uint32_t W1l = smem_u32(smem + 3 * ARR_U32);
    const uint32_t W2h = smem_u32(smem + 4 * ARR_U32);
    const uint32_t W2l = smem_u32(smem + 5 * ARR_U32);
    stage_W(w1h, W1h, t);
    stage_W(w1l, W1l, t);
    stage_W(w2h, W2h, t);
    stage_W(w2l, W2l, t);
    asm volatile("cp.async.commit_group;" ::: "memory");

    uint32_t aoff[2], boff[2];
#pragma unroll
    for (int mt = 0; mt < 2; mt++) {
        int row = wm * 32 + mt * 16 + ((lane >> 3) & 1) * 8 + (lane & 7);
        aoff[mt] = row * 272 + (lane >> 4) * 16;
    }
#pragma unroll
    for (int np = 0; np < 2; np++) {
        int row = wn * 32 + np * 16 + (lane >> 4) * 8 + (lane & 7);
        boff[np] = row * 272 + ((lane >> 3) & 1) * 16;
    }
    const uint32_t Ahi = smem_u32(As_hi), Alo = smem_u32(As_lo);
    const int g = lane >> 2;
    const int c2 = (lane & 3) * 2;
    const int srow = t >> 2, sq = t & 3;

    // prologue: prefetch first tile
    int tile = blockIdx.x;
    float4 px[8];
    prefetch_A(A, tile * 128 + srow, sq, px);
    asm volatile("cp.async.wait_group 0;" ::: "memory");

    for (int it = 0; tile < NT_TILES; tile += gridDim.x, ++it) {
        const int row0 = tile * 128;
        const int gr = row0 + srow;

        // stage current tile from registers (+agg +affine +combine)
        {
            const float4* Gr = reinterpret_cast<const float4*>(g_agg + (size_t)gr * D);
#pragma unroll
            for (int j = 0; j < 8; j++) {
                int f4 = sq * 8 + j;
                float4 v = make_float4(0.f, 0.f, 0.f, 0.f);
                if (gr < N_NODES) {
                    v = px[j];
                    if (AFF) {
                        float4 a = *reinterpret_cast<const float4*>(g_bn + f4 * 4);
                        float4 c = *reinterpret_cast<const float4*>(g_bn + D + f4 * 4);
                        v.x = a.x * v.x + c.x; v.y = a.y * v.y + c.y;
                        v.z = a.z * v.z + c.z; v.w = a.w * v.w + c.w;
                    }
                    float4 q4 = Gr[f4];
                    v.x = cA * v.x + q4.x; v.y = cA * v.y + q4.y;
                    v.z = cA * v.z + q4.z; v.w = cA * v.w + q4.w;
                }
                uint32_t h0, l0, h1, l1;
                split2(v.x, v.y, h0, l0);
                split2(v.z, v.w, h1, l1);
                int o = srow * ROW_U32 + f4 * 2;
                *reinterpret_cast<uint2*>(&As_hi[o]) = make_uint2(h0, h1);
                *reinterpret_cast<uint2*>(&As_lo[o]) = make_uint2(l0, l1);
            }
        }
        __syncthreads();

        float acc[2][4][4];
#pragma unroll
        for (int mt = 0; mt < 2; mt++)
#pragma unroll
            for (int nt = 0; nt < 4; nt++)
#pragma unroll
                for (int i = 0; i < 4; i++) acc[mt][nt][i] = 0.f;

        // ---- GEMM1 ----
        mma_3pass(acc, Ahi, Alo, W1h, W1l, aoff, boff);

        // prefetch next tile's A rows (no smem; overlaps barrier+epi1+GEMM2)
        const int ntile = tile + gridDim.x;
        if (ntile < NT_TILES) prefetch_A(A, ntile * 128 + srow, sq, px);

        __syncthreads();   // B0: all GEMM1 reads of As done

        // epilogue1: P = relu(acc+b1) -> bf16 hi/lo back into As
#pragma unroll
        for (int mt = 0; mt < 2; mt++) {
            int ra = wm * 32 + mt * 16 + g;
            int rb = ra + 8;
#pragma unroll
            for (int nt = 0; nt < 4; nt++) {
                int col = wn * 32 + nt * 8 + c2;
                int o = col >> 1;
                float t0 = fmaxf(acc[mt][nt][0] + sb1[col], 0.f);
                float t1 = fmaxf(acc[mt][nt][1] + sb1[col + 1], 0.f);
                float t2 = fmaxf(acc[mt][nt][2] + sb1[col], 0.f);
                float t3 = fmaxf(acc[mt][nt][3] + sb1[col + 1], 0.f);
                uint32_t hi, lo;
                split2(t0, t1, hi, lo);
                As_hi[ra * ROW_U32 + o] = hi;
                As_lo[ra * ROW_U32 + o] = lo;
                split2(t2, t3, hi, lo);
                As_hi[rb * ROW_U32 + o] = hi;
                As_lo[rb * ROW_U32 + o] = lo;
#pragma unroll
                for (int i = 0; i < 4; i++) acc[mt][nt][i] = 0.f;
            }
        }
        __syncthreads();   // B1: P staged

        // ---- GEMM2 ----
        mma_3pass(acc, Ahi, Alo, W2h, W2l, aoff, boff);

        // epilogue2: relu+bias, store h, accumulate column stats
        {
            float sp[4][2], qp[4][2];
#pragma unroll
            for (int nt = 0; nt < 4; nt++) {
                sp[nt][0] = sp[nt][1] = 0.f;
                qp[nt][0] = qp[nt][1] = 0.f;
            }
#pragma unroll
            for (int mt = 0; mt < 2; mt++) {
                int ra = row0 + wm * 32 + mt * 16 + g;
                int rb = ra + 8;
#pragma unroll
                for (int nt = 0; nt < 4; nt++) {
                    int col = wn * 32 + nt * 8 + c2;
                    float v0 = fmaxf(acc[mt][nt][0] + sb2[col], 0.f);
                    float v1 = fmaxf(acc[mt][nt][1] + sb2[col + 1], 0.f);
                    float v2 = fmaxf(acc[mt][nt][2] + sb2[col], 0.f);
                    float v3 = fmaxf(acc[mt][nt][3] + sb2[col + 1], 0.f);
                    if (ra < N_NODES) {
                        *reinterpret_cast<float2*>(out + (size_t)ra * D + col) =
                            make_float2(v0, v1);
                        sp[nt][0] += v0; sp[nt][1] += v1;
                        qp[nt][0] += v0 * v0; qp[nt][1] += v1 * v1;
                    }
                    if (rb < N_NODES) {
                        *reinterpret_cast<float2*>(out + (size_t)rb * D + col) =
                            make_float2(v2, v3);
                        sp[nt][0] += v2; sp[nt][1] += v3;
                        qp[nt][0] += v2 * v2; qp[nt][1] += v3 * v3;
                    }
                }
            }
#pragma unroll
            for (int nt = 0; nt < 4; nt++) {
#pragma unroll
                for (int d = 4; d < 32; d <<= 1) {
                    sp[nt][0] += __shfl_xor_sync(0xffffffffu, sp[nt][0], d);
                    sp[nt][1] += __shfl_xor_sync(0xffffffffu, sp[nt][1], d);
                    qp[nt][0] += __shfl_xor_sync(0xffffffffu, qp[nt][0], d);
                    qp[nt][1] += __shfl_xor_sync(0xffffffffu, qp[nt][1], d);
                }
            }
            if (g == 0) {
#pragma unroll
                for (int nt = 0; nt < 4; nt++) {
                    int col = wn * 32 + nt * 8 + c2;
                    atomicAdd(&s_sum[col], sp[nt][0]);
                    atomicAdd(&s_sum[col + 1], sp[nt][1]);
                    atomicAdd(&s_sq[col], qp[nt][0]);
                    atomicAdd(&s_sq[col + 1], qp[nt][1]);
                }
            }
        }
        __syncthreads();   // B2: As reuse next tile
    }

    if (t < D) {
        asm volatile("red.global.add.f32 [%0], %1;" :: "l"(&g_colsum[t]), "f"(s_sum[t]) : "memory");
        asm volatile("red.global.add.f32 [%0], %1;" :: "l"(&g_colsq[t]), "f"(s_sq[t]) : "memory");
    }
}

// ---------------------------------------------------------------------------
// Persistent final linear: t = relu((a*h+c) @ Wl^T + bl), bf16 3-pass
// ---------------------------------------------------------------------------
__global__ void __launch_bounds__(512) k_gemm_l(const float* __restrict__ A,
                                                const float* __restrict__ bias,
                                                const __nv_bfloat16* __restrict__ wh,
                                                const __nv_bfloat16* __restrict__ wl,
                                                float* __restrict__ out) {
    extern __shared__ uint32_t smem[];
    uint32_t* As_hi = smem;
    uint32_t* As_lo = smem + ARR_U32;
    __shared__ float sb[D];

    const int t = threadIdx.x, warp = t >> 5, lane = t & 31;
    const int wm = warp & 3, wn = warp >> 2;

    if (t < D) sb[t] = __ldg(bias + t);

    const uint32_t Wh = smem_u32(smem + 2 * ARR_U32);
    const uint32_t Wl = smem_u32(smem + 3 * ARR_U32);
    stage_W(wh, Wh, t);
    stage_W(wl, Wl, t);
    asm volatile("cp.async.commit_group;" ::: "memory");

    uint32_t aoff[2], boff[2];
#pragma unroll
    for (int mt = 0; mt < 2; mt++) {
        int row = wm * 32 + mt * 16 + ((lane >> 3) & 1) * 8 + (lane & 7);
        aoff[mt] = row * 272 + (lane >> 4) * 16;
    }
#pragma unroll
    for (int np = 0; np < 2; np++) {
        int row = wn * 32 + np * 16 + (lane >> 4) * 8 + (lane & 7);
        boff[np] = row * 272 + ((lane >> 3) & 1) * 16;
    }
    const uint32_t Ahi = smem_u32(As_hi), Alo = smem_u32(As_lo);
    const int g = lane >> 2;
    const int c2 = (lane & 3) * 2;
    const int srow = t >> 2, sq = t & 3;

    int tile = blockIdx.x;
    float4 px[8];
    prefetch_A(A, tile * 128 + srow, sq, px);
    asm volatile("cp.async.wait_group 0;" ::: "memory");

    for (; tile < NT_TILES; tile += gridDim.x) {
        const int row0 = tile * 128;
        const int gr = row0 + srow;

        // stage current tile from registers (+BN affine)
#pragma unroll
        for (int j = 0; j < 8; j++) {
            int f4 = sq * 8 + j;
            float4 v = make_float4(0.f, 0.f, 0.f, 0.f);
            if (gr < N_NODES) {
                v = px[j];
                float4 a = *reinterpret_cast<const float4*>(g_bn + f4 * 4);
                float4 c = *reinterpret_cast<const float4*>(g_bn + D + f4 * 4);
                v.x = a.x * v.x + c.x; v.y = a.y * v.y + c.y;
                v.z = a.z * v.z + c.z; v.w = a.w * v.w + c.w;
            }
            uint32_t h0, l0, h1, l1;
            split2(v.x, v.y, h0, l0);
            split2(v.z, v.w, h1, l1);
            int o = srow * ROW_U32 + f4 * 2;
            *reinterpret_cast<uint2*>(&As_hi[o]) = make_uint2(h0, h1);
            *reinterpret_cast<uint2*>(&As_lo[o]) = make_uint2(l0, l1);
        }
        __syncthreads();

        float acc[2][4][4];
#pragma unroll
        for (int mt = 0; mt < 2; mt++)
#pragma unroll
            for (int nt = 0; nt < 4; nt++)
#pragma unroll
                for (int i = 0; i < 4; i++) acc[mt][nt][i] = 0.f;

        mma_3pass(acc, Ahi, Alo, Wh, Wl, aoff, boff);

        const int ntile = tile + gridDim.x;
        if (ntile < NT_TILES) prefetch_A(A, ntile * 128 + srow, sq, px);

        // epilogue: bias + relu + store
#pragma unroll
        for (int mt = 0; mt < 2; mt++) {
            int ra = row0 + wm * 32 + mt * 16 + g;
            int rb = ra + 8;
#pragma unroll
            for (int nt = 0; nt < 4; nt++) {
                int col = wn * 32 + nt * 8 + c2;
                if (ra < N_NODES)
                    *reinterpret_cast<float2*>(out + (size_t)ra * D + col) =
                        make_float2(fmaxf(acc[mt][nt][0] + sb[col], 0.f),
                                    fmaxf(acc[mt][nt][1] + sb[col + 1], 0.f));
                if (rb < N_NODES)
                    *reinterpret_cast<float2*>(out + (size_t)rb * D + col) =
                        make_float2(fmaxf(acc[mt][nt][2] + sb[col], 0.f),
                                    fmaxf(acc[mt][nt][3] + sb[col + 1], 0.f));
            }
        }
        __syncthreads();   // As reuse next tile
    }
}

// ---------------------------------------------------------------------------
__global__ void k_bnprep(const float* __restrict__ gamma,
                         const float* __restrict__ beta) {
    int t = threadIdx.x;
    float inv_n = 1.0f / (float)N_NODES;
    float mu = g_colsum[t] * inv_n;
    float var = g_colsq[t] * inv_n - mu * mu;
    float a = gamma[t] * rsqrtf(var + 1e-5f);
    g_bn[t] = a;
    g_bn[D + t] = beta[t] - mu * a;
}

// ---------------------------------------------------------------------------
__global__ void __launch_bounds__(256) k_pairs(const float* __restrict__ h,
                                               const int* __restrict__ pairs,
                                               const float* __restrict__ Wfc,
                                               const float* __restrict__ bfc,
                                               float* __restrict__ out) {
    __shared__ float sW[O_OUT][D];
    __shared__ float sb[O_OUT];
    int t = threadIdx.x;
    for (int i = t; i < O_OUT * D; i += 256) sW[i / D][i % D] = Wfc[i];
    if (t < O_OUT) sb[t] = bfc[t];
    __syncthreads();

    int p = (blockIdx.x * 256 + t) >> 5;
    int lane = t & 31;
    if (p >= P_PAIRS) return;

    int i0 = pairs[2 * p];
    int i1 = pairs[2 * p + 1];
    float4 u = reinterpret_cast<const float4*>(h + (size_t)i0 * D)[lane];
    float4 v = reinterpret_cast<const float4*>(h + (size_t)i1 * D)[lane];
    float4 w = make_float4(u.x * v.x, u.y * v.y, u.z * v.z, u.w * v.w);

    float s[O_OUT];
#pragma unroll
    for (int o = 0; o < O_OUT; o++)
        s[o] = w.x * sW[o][4 * lane + 0] + w.y * sW[o][4 * lane + 1] +
               w.z * sW[o][4 * lane + 2] + w.w * sW[o][4 * lane + 3];
#pragma unroll
    for (int o = 0; o < O_OUT; o++)
#pragma unroll
        for (int off = 16; off > 0; off >>= 1)
            s[o] += __shfl_xor_sync(0xffffffffu, s[o], off);
    if (lane == 0)
#pragma unroll
        for (int o = 0; o < O_OUT; o++) out[(size_t)p * O_OUT + o] = s[o] + sb[o];
}

// ---------------------------------------------------------------------------
extern "C" void kernel_launch(void* const* d_in, const int* in_sizes, int n_in,
                              void* d_out, int out_size) {
    const float* x    = (const float*)d_in[0];
    const float* W1a  = (const float*)d_in[1];
    const float* b1a  = (const float*)d_in[2];
    const float* W2a  = (const float*)d_in[3];
    const float* b2a  = (const float*)d_in[4];
    const float* g0   = (const float*)d_in[5];
    const float* bt0  = (const float*)d_in[6];
    const float* eps0 = (const float*)d_in[7];
    const float* W1b  = (const float*)d_in[8];
    const float* b1b  = (const float*)d_in[9];
    const float* W2b  = (const float*)d_in[10];
    const float* b2b  = (const float*)d_in[11];
    const float* g1   = (const float*)d_in[12];
    const float* bt1  = (const float*)d_in[13];
    const float* eps1 = (const float*)d_in[14];
    const float* Wl   = (const float*)d_in[15];
    const float* bl   = (const float*)d_in[16];
    const float* Wfc  = (const float*)d_in[17];
    const float* bfc  = (const float*)d_in[18];
    const int* esrc   = (const int*)d_in[19];
    const int* edst   = (const int*)d_in[20];
    const int* pairs  = (const int*)d_in[21];
    float* out = (float*)d_out;

    float *t, *h;
    __nv_bfloat16 *wh, *wl;
    cudaGetSymbolAddress((void**)&t, g_t);
    cudaGetSymbolAddress((void**)&h, g_h);
    cudaGetSymbolAddress((void**)&wh, g_wh);
    cudaGetSymbolAddress((void**)&wl, g_wl);

    cudaFuncSetAttribute(k_mlp<0>, cudaFuncAttributeMaxDynamicSharedMemorySize, SMEM_MLP);
    cudaFuncSetAttribute(k_mlp<1>, cudaFuncAttributeMaxDynamicSharedMemorySize, SMEM_MLP);
    cudaFuncSetAttribute(k_gemm_l, cudaFuncAttributeMaxDynamicSharedMemorySize, SMEM_GL);

    const int ZB = (N_NODES * D / 4 + 255) / 256;
    const int SB = (E_EDGES * 32 + 255) / 256;
    const int PB = (P_PAIRS * 32) / 256;
    const int WS = D * D;
    const int PG = 148;

    k_prep_w<<<(5 * WS + 255) / 256, 256>>>(W1a, W2a, W1b, W2b, Wl);

    // Layer A
    k_zero<<<ZB, 256>>>();
    k_scatter<0><<<SB, 256>>>(x, esrc, edst);
    k_mlp<0><<<PG, 512, SMEM_MLP>>>(x, eps0, b1a, b2a,
                                    wh + 0 * WS, wl + 0 * WS,
                                    wh + 1 * WS, wl + 1 * WS, h);
    k_bnprep<<<1, 128>>>(g0, bt0);

    // Layer B (BN-A affine folded into scatter + mlp stage)
    k_zero<<<ZB, 256>>>();
    k_scatter<1><<<SB, 256>>>(h, esrc, edst);
    k_mlp<1><<<PG, 512, SMEM_MLP>>>(h, eps1, b1b, b2b,
                                    wh + 2 * WS, wl + 2 * WS,
                                    wh + 3 * WS, wl + 3 * WS, h);
    k_bnprep<<<1, 128>>>(g1, bt1);

    // Final linear (BN-B affine folded) + pair head
    k_gemm_l<<<PG, 512, SMEM_GL>>>(h, bl, wh + 4 * WS, wl + 4 * WS, t);
    k_pairs<<<PB, 256>>>(t, pairs, Wfc, bfc, out);
}

// round 9
// speedup vs baseline: 2.1453x; 1.0058x over previous
#include <cuda_runtime.h>
#include <cuda_bf16.h>
#include <cstdint>

#define N_NODES 50000
#define D 128
#define E_EDGES 600000
#define P_PAIRS 131072
#define O_OUT 7
#define NT_TILES 391                         // ceil(N/128)

#define ROW_U32 68                           // padded row: 68 u32 = 272 B
#define ARR_U32 (128 * ROW_U32)
#define ARR_BYTES (ARR_U32 * 4)
#define SMEM_MLP (6 * ARR_BYTES)             // A(hi,lo) W1(hi,lo) W2(hi,lo)
#define SMEM_GL  (4 * ARR_BYTES)

// Scratch
__device__ float g_agg[N_NODES * D];
__device__ float g_t[N_NODES * D];
__device__ float g_h[N_NODES * D];
__device__ float g_colsum[D];
__device__ float g_colsq[D];
__device__ float g_bn[2 * D];                // [0:128) a, [128:256) c
__device__ __nv_bfloat16 g_wh[5 * D * D];    // dense pre-split weights (hi)
__device__ __nv_bfloat16 g_wl[5 * D * D];    // (lo residual)

// ---------------------------------------------------------------------------
__global__ void k_prep_w(const float* __restrict__ w0, const float* __restrict__ w1,
                         const float* __restrict__ w2, const float* __restrict__ w3,
                         const float* __restrict__ w4) {
    int i = blockIdx.x * blockDim.x + threadIdx.x;
    if (i >= 5 * D * D) return;
    const float* srcs[5] = {w0, w1, w2, w3, w4};
    float v = srcs[i >> 14][i & 16383];
    __nv_bfloat16 h = __float2bfloat16(v);
    g_wh[i] = h;
    g_wl[i] = __float2bfloat16(v - __bfloat162float(h));
}

__global__ void k_zero() {
    int i = blockIdx.x * blockDim.x + threadIdx.x;
    if (i < N_NODES * D / 4)
        reinterpret_cast<float4*>(g_agg)[i] = make_float4(0.f, 0.f, 0.f, 0.f);
    if (blockIdx.x == 0 && threadIdx.x < D) {
        g_colsum[threadIdx.x] = 0.f;
        g_colsq[threadIdx.x] = 0.f;
    }
}

// ---------------------------------------------------------------------------
// Edge scatter: agg[dst] += f(h[src]); AFF folds BN affine
// ---------------------------------------------------------------------------
template <int AFF>
__global__ void k_scatter(const float* __restrict__ h,
                          const int* __restrict__ src,
                          const int* __restrict__ dst) {
    int e = (blockIdx.x * blockDim.x + threadIdx.x) >> 5;
    int lane = threadIdx.x & 31;
    if (e >= E_EDGES) return;
    int s = src[e];
    int d = dst[e];
    float4 v = reinterpret_cast<const float4*>(h + (size_t)s * D)[lane];
    if (AFF) {
        float4 a = *reinterpret_cast<const float4*>(g_bn + lane * 4);
        float4 c = *reinterpret_cast<const float4*>(g_bn + D + lane * 4);
        v.x = a.x * v.x + c.x;
        v.y = a.y * v.y + c.y;
        v.z = a.z * v.z + c.z;
        v.w = a.w * v.w + c.w;
    }
    float* o = g_agg + (size_t)d * D + lane * 4;
    asm volatile("red.global.add.v4.f32 [%0], {%1,%2,%3,%4};"
                 :: "l"(o), "f"(v.x), "f"(v.y), "f"(v.z), "f"(v.w) : "memory");
}

// ---------------------------------------------------------------------------
// MMA helpers.
// ldmatrix: non-volatile + "memory" clobber — ordered vs smem stores and
// __syncthreads(), but the pure-register MMAs may be scheduled freely
// between/around fragment loads.
// mma: non-volatile, registers only.
// ---------------------------------------------------------------------------
static __device__ __forceinline__ uint32_t smem_u32(const void* p) {
    return (uint32_t)__cvta_generic_to_shared(p);
}
static __device__ __forceinline__ void split2(float a, float b, uint32_t& hi, uint32_t& lo) {
    __nv_bfloat162 h = __floats2bfloat162_rn(a, b);
    float ra = a - __bfloat162float(h.x);
    float rb = b - __bfloat162float(h.y);
    __nv_bfloat162 l = __floats2bfloat162_rn(ra, rb);
    hi = *reinterpret_cast<uint32_t*>(&h);
    lo = *reinterpret_cast<uint32_t*>(&l);
}
static __device__ __forceinline__ void ldmx4(uint32_t addr, uint32_t r[4]) {
    asm("ldmatrix.sync.aligned.m8n8.x4.shared.b16 {%0,%1,%2,%3}, [%4];"
        : "=r"(r[0]), "=r"(r[1]), "=r"(r[2]), "=r"(r[3]) : "r"(addr) : "memory");
}
static __device__ __forceinline__ void mma16816(float c[4], const uint32_t a[4],
                                                uint32_t b0, uint32_t b1) {
    asm("mma.sync.aligned.m16n8k16.row.col.f32.bf16.bf16.f32 "
        "{%0,%1,%2,%3},{%4,%5,%6,%7},{%8,%9},{%0,%1,%2,%3};"
        : "+f"(c[0]), "+f"(c[1]), "+f"(c[2]), "+f"(c[3])
        : "r"(a[0]), "r"(a[1]), "r"(a[2]), "r"(a[3]), "r"(b0), "r"(b1));
}
static __device__ __forceinline__ void cpa16(uint32_t dst, const void* src) {
    asm volatile("cp.async.cg.shared.global [%0], [%1], 16;"
                 :: "r"(dst), "l"(src) : "memory");
}

// 3-pass GEMM body (hi*hi + hi*lo + lo*hi), pass-major MMA order.
static __device__ __forceinline__ void mma_3pass(float acc[2][4][4],
                                                 uint32_t Ahi, uint32_t Alo,
                                                 uint32_t Bhi, uint32_t Blo,
                                                 const uint32_t aoff[2],
                                                 const uint32_t boff[2]) {
#pragma unroll
    for (int ks = 0; ks < 8; ks++) {
        uint32_t kb = ks * 32;
        uint32_t ah[2][4], al[2][4], bh[2][4], bl[2][4];
#pragma unroll
        for (int mt = 0; mt < 2; mt++) {
            ldmx4(Ahi + aoff[mt] + kb, ah[mt]);
            ldmx4(Alo + aoff[mt] + kb, al[mt]);
        }
#pragma unroll
        for (int np = 0; np < 2; np++) {
            ldmx4(Bhi + boff[np] + kb, bh[np]);
            ldmx4(Blo + boff[np] + kb, bl[np]);
        }
#pragma unroll
        for (int mt = 0; mt < 2; mt++)
#pragma unroll
            for (int nt = 0; nt < 4; nt++) {
                int np = nt >> 1, o = (nt & 1) * 2;
                mma16816(acc[mt][nt], ah[mt], bh[np][o], bh[np][o + 1]);
            }
#pragma unroll
        for (int mt = 0; mt < 2; mt++)
#pragma unroll
            for (int nt = 0; nt < 4; nt++) {
                int np = nt >> 1, o = (nt & 1) * 2;
                mma16816(acc[mt][nt], ah[mt], bl[np][o], bl[np][o + 1]);
            }
#pragma unroll
        for (int mt = 0; mt < 2; mt++)
#pragma unroll
            for (int nt = 0; nt < 4; nt++) {
                int np = nt >> 1, o = (nt & 1) * 2;
                mma16816(acc[mt][nt], al[mt], bh[np][o], bh[np][o + 1]);
            }
    }
}

// cp.async one dense 128x128 bf16 weight array into padded smem (512 thr)
static __device__ __forceinline__ void stage_W(const __nv_bfloat16* __restrict__ w,
                                               uint32_t dbase, int t) {
#pragma unroll
    for (int it = 0; it < 4; it++) {
        int c = t + it * 512;                 // 0..2047
        int row = c >> 4, j = c & 15;
        cpa16(dbase + row * 272 + j * 16, w + row * D + j * 8);
    }
}

// prefetch one tile's A rows into registers (8 float4 per thread, 512 thr)
static __device__ __forceinline__ void prefetch_A(const float* __restrict__ A,
                                                  int gr, int sq, float4 px[8]) {
    if (gr < N_NODES) {
        const float4* Ar = reinterpret_cast<const float4*>(A + (size_t)gr * D);
#pragma unroll
        for (int j = 0; j < 8; j++) px[j] = Ar[sq * 8 + j];
    }
}

// ---------------------------------------------------------------------------
// Persistent fused GIN MLP (512 threads), bf16 3-pass, A register-prefetch
// ---------------------------------------------------------------------------
template <int AFF>
__global__ void __launch_bounds__(512) k_mlp(const float* __restrict__ A,
                                             const float* __restrict__ epsp,
                                             const float* __restrict__ b1,
                                             const float* __restrict__ b2,
                                             const __nv_bfloat16* __restrict__ w1h,
                                             const __nv_bfloat16* __restrict__ w1l,
                                             const __nv_bfloat16* __restrict__ w2h,
                                             const __nv_bfloat16* __restrict__ w2l,
                                             float* __restrict__ out) {
    extern __shared__ uint32_t smem[];
    uint32_t* As_hi = smem;
    uint32_t* As_lo = smem + ARR_U32;
    __shared__ float sb1[D], sb2[D], s_sum[D], s_sq[D];

    const int t = threadIdx.x, warp = t >> 5, lane = t & 31;
    const int wm = warp & 3, wn = warp >> 2;
    const float cA = 1.0f + *epsp;

    if (t < D) {
        sb1[t] = __ldg(b1 + t);
        sb2[t] = __ldg(b2 + t);
        s_sum[t] = 0.f;
        s_sq[t] = 0.f;
    }

    const uint32_t W1h = smem_u32(smem + 2 * ARR_U32);
    const uint32_t W1l = smem_u32(smem + 3 * ARR_U32);
    const uint32_t W2h = smem_u32(smem + 4 * ARR_U32);
    const uint32_t W2l = smem_u32(smem + 5 * ARR_U32);
    stage_W(w1h, W1h, t);
    stage_W(w1l, W1l, t);
    stage_W(w2h, W2h, t);
    stage_W(w2l, W2l, t);
    asm volatile("cp.async.commit_group;" ::: "memory");

    uint32_t aoff[2], boff[2];
#pragma unroll
    for (int mt = 0; mt < 2; mt++) {
        int row = wm * 32 + mt * 16 + ((lane >> 3) & 1) * 8 + (lane & 7);
        aoff[mt] = row * 272 + (lane >> 4) * 16;
    }
#pragma unroll
    for (int np = 0; np < 2; np++) {
        int row = wn * 32 + np * 16 + (lane >> 4) * 8 + (lane & 7);
        boff[np] = row * 272 + ((lane >> 3) & 1) * 16;
    }
    const uint32_t Ahi = smem_u32(As_hi), Alo = smem_u32(As_lo);
    const int g = lane >> 2;
    const int c2 = (lane & 3) * 2;
    const int srow = t >> 2, sq = t & 3;

    // prologue: prefetch first tile
    int tile = blockIdx.x;
    float4 px[8];
    prefetch_A(A, tile * 128 + srow, sq, px);
    asm volatile("cp.async.wait_group 0;" ::: "memory");

    for (; tile < NT_TILES; tile += gridDim.x) {
        const int row0 = tile * 128;
        const int gr = row0 + srow;

        // stage current tile from registers (+agg +affine +combine)
        {
            const float4* Gr = reinterpret_cast<const float4*>(g_agg + (size_t)gr * D);
#pragma unroll
            for (int j = 0; j < 8; j++) {
                int f4 = sq * 8 + j;
                float4 v = make_float4(0.f, 0.f, 0.f, 0.f);
                if (gr < N_NODES) {
                    v = px[j];
                    if (AFF) {
                        float4 a = *reinterpret_cast<const float4*>(g_bn + f4 * 4);
                        float4 c = *reinterpret_cast<const float4*>(g_bn + D + f4 * 4);
                        v.x = a.x * v.x + c.x; v.y = a.y * v.y + c.y;
                        v.z = a.z * v.z + c.z; v.w = a.w * v.w + c.w;
                    }
                    float4 q4 = Gr[f4];
                    v.x = cA * v.x + q4.x; v.y = cA * v.y + q4.y;
                    v.z = cA * v.z + q4.z; v.w = cA * v.w + q4.w;
                }
                uint32_t h0, l0, h1, l1;
                split2(v.x, v.y, h0, l0);
                split2(v.z, v.w, h1, l1);
                int o = srow * ROW_U32 + f4 * 2;
                *reinterpret_cast<uint2*>(&As_hi[o]) = make_uint2(h0, h1);
                *reinterpret_cast<uint2*>(&As_lo[o]) = make_uint2(l0, l1);
            }
        }
        __syncthreads();

        float acc[2][4][4];
#pragma unroll
        for (int mt = 0; mt < 2; mt++)
#pragma unroll
            for (int nt = 0; nt < 4; nt++)
#pragma unroll
                for (int i = 0; i < 4; i++) acc[mt][nt][i] = 0.f;

        // ---- GEMM1 ----
        mma_3pass(acc, Ahi, Alo, W1h, W1l, aoff, boff);

        // prefetch next tile's A rows (overlaps barrier+epi1+GEMM2)
        const int ntile = tile + gridDim.x;
        if (ntile < NT_TILES) prefetch_A(A, ntile * 128 + srow, sq, px);

        __syncthreads();   // B0: all GEMM1 reads of As done

        // epilogue1: P = relu(acc+b1) -> bf16 hi/lo back into As
#pragma unroll
        for (int mt = 0; mt < 2; mt++) {
            int ra = wm * 32 + mt * 16 + g;
            int rb = ra + 8;
#pragma unroll
            for (int nt = 0; nt < 4; nt++) {
                int col = wn * 32 + nt * 8 + c2;
                int o = col >> 1;
                float t0 = fmaxf(acc[mt][nt][0] + sb1[col], 0.f);
                float t1 = fmaxf(acc[mt][nt][1] + sb1[col + 1], 0.f);
                float t2 = fmaxf(acc[mt][nt][2] + sb1[col], 0.f);
                float t3 = fmaxf(acc[mt][nt][3] + sb1[col + 1], 0.f);
                uint32_t hi, lo;
                split2(t0, t1, hi, lo);
                As_hi[ra * ROW_U32 + o] = hi;
                As_lo[ra * ROW_U32 + o] = lo;
                split2(t2, t3, hi, lo);
                As_hi[rb * ROW_U32 + o] = hi;
                As_lo[rb * ROW_U32 + o] = lo;
#pragma unroll
                for (int i = 0; i < 4; i++) acc[mt][nt][i] = 0.f;
            }
        }
        __syncthreads();   // B1: P staged

        // ---- GEMM2 ----
        mma_3pass(acc, Ahi, Alo, W2h, W2l, aoff, boff);

        // epilogue2: relu+bias, store h, accumulate column stats
        {
            float sp[4][2], qp[4][2];
#pragma unroll
            for (int nt = 0; nt < 4; nt++) {
                sp[nt][0] = sp[nt][1] = 0.f;
                qp[nt][0] = qp[nt][1] = 0.f;
            }
#pragma unroll
            for (int mt = 0; mt < 2; mt++) {
                int ra = row0 + wm * 32 + mt * 16 + g;
                int rb = ra + 8;
#pragma unroll
                for (int nt = 0; nt < 4; nt++) {
                    int col = wn * 32 + nt * 8 + c2;
                    float v0 = fmaxf(acc[mt][nt][0] + sb2[col], 0.f);
                    float v1 = fmaxf(acc[mt][nt][1] + sb2[col + 1], 0.f);
                    float v2 = fmaxf(acc[mt][nt][2] + sb2[col], 0.f);
                    float v3 = fmaxf(acc[mt][nt][3] + sb2[col + 1], 0.f);
                    if (ra < N_NODES) {
                        *reinterpret_cast<float2*>(out + (size_t)ra * D + col) =
                            make_float2(v0, v1);
                        sp[nt][0] += v0; sp[nt][1] += v1;
                        qp[nt][0] += v0 * v0; qp[nt][1] += v1 * v1;
                    }
                    if (rb < N_NODES) {
                        *reinterpret_cast<float2*>(out + (size_t)rb * D + col) =
                            make_float2(v2, v3);
                        sp[nt][0] += v2; sp[nt][1] += v3;
                        qp[nt][0] += v2 * v2; qp[nt][1] += v3 * v3;
                    }
                }
            }
#pragma unroll
            for (int nt = 0; nt < 4; nt++) {
#pragma unroll
                for (int d = 4; d < 32; d <<= 1) {
                    sp[nt][0] += __shfl_xor_sync(0xffffffffu, sp[nt][0], d);
                    sp[nt][1] += __shfl_xor_sync(0xffffffffu, sp[nt][1], d);
                    qp[nt][0] += __shfl_xor_sync(0xffffffffu, qp[nt][0], d);
                    qp[nt][1] += __shfl_xor_sync(0xffffffffu, qp[nt][1], d);
                }
            }
            if (g == 0) {
#pragma unroll
                for (int nt = 0; nt < 4; nt++) {
                    int col = wn * 32 + nt * 8 + c2;
                    atomicAdd(&s_sum[col], sp[nt][0]);
                    atomicAdd(&s_sum[col + 1], sp[nt][1]);
                    atomicAdd(&s_sq[col], qp[nt][0]);
                    atomicAdd(&s_sq[col + 1], qp[nt][1]);
                }
            }
        }
        __syncthreads();   // B2: As reuse next tile
    }

    if (t < D) {
        asm volatile("red.global.add.f32 [%0], %1;" :: "l"(&g_colsum[t]), "f"(s_sum[t]) : "memory");
        asm volatile("red.global.add.f32 [%0], %1;" :: "l"(&g_colsq[t]), "f"(s_sq[t]) : "memory");
    }
}

// ---------------------------------------------------------------------------
// Persistent final linear: t = relu((a*h+c) @ Wl^T + bl), bf16 3-pass
// ---------------------------------------------------------------------------
__global__ void __launch_bounds__(512) k_gemm_l(const float* __restrict__ A,
                                                const float* __restrict__ bias,
                                                const __nv_bfloat16* __restrict__ wh,
                                                const __nv_bfloat16* __restrict__ wl,
                                                float* __restrict__ out) {
    extern __shared__ uint32_t smem[];
    uint32_t* As_hi = smem;
    uint32_t* As_lo = smem + ARR_U32;
    __shared__ float sb[D];

    const int t = threadIdx.x, warp = t >> 5, lane = t & 31;
    const int wm = warp & 3, wn = warp >> 2;

    if (t < D) sb[t] = __ldg(bias + t);

    const uint32_t Wh = smem_u32(smem + 2 * ARR_U32);
    const uint32_t Wl = smem_u32(smem + 3 * ARR_U32);
    stage_W(wh, Wh, t);
    stage_W(wl, Wl, t);
    asm volatile("cp.async.commit_group;" ::: "memory");

    uint32_t aoff[2], boff[2];
#pragma unroll
    for (int mt = 0; mt < 2; mt++) {
        int row = wm * 32 + mt * 16 + ((lane >> 3) & 1) * 8 + (lane & 7);
        aoff[mt] = row * 272 + (lane >> 4) * 16;
    }
#pragma unroll
    for (int np = 0; np < 2; np++) {
        int row = wn * 32 + np * 16 + (lane >> 4) * 8 + (lane & 7);
        boff[np] = row * 272 + ((lane >> 3) & 1) * 16;
    }
    const uint32_t Ahi = smem_u32(As_hi), Alo = smem_u32(As_lo);
    const int g = lane >> 2;
    const int c2 = (lane & 3) * 2;
    const int srow = t >> 2, sq = t & 3;

    int tile = blockIdx.x;
    float4 px[8];
    prefetch_A(A, tile * 128 + srow, sq, px);
    asm volatile("cp.async.wait_group 0;" ::: "memory");

    for (; tile < NT_TILES; tile += gridDim.x) {
        const int row0 = tile * 128;
        const int gr = row0 + srow;

        // stage current tile from registers (+BN affine)
#pragma unroll
        for (int j = 0; j < 8; j++) {
            int f4 = sq * 8 + j;
            float4 v = make_float4(0.f, 0.f, 0.f, 0.f);
            if (gr < N_NODES) {
                v = px[j];
                float4 a = *reinterpret_cast<const float4*>(g_bn + f4 * 4);
                float4 c = *reinterpret_cast<const float4*>(g_bn + D + f4 * 4);
                v.x = a.x * v.x + c.x; v.y = a.y * v.y + c.y;
                v.z = a.z * v.z + c.z; v.w = a.w * v.w + c.w;
            }
            uint32_t h0, l0, h1, l1;
            split2(v.x, v.y, h0, l0);
            split2(v.z, v.w, h1, l1);
            int o = srow * ROW_U32 + f4 * 2;
            *reinterpret_cast<uint2*>(&As_hi[o]) = make_uint2(h0, h1);
            *reinterpret_cast<uint2*>(&As_lo[o]) = make_uint2(l0, l1);
        }
        __syncthreads();

        float acc[2][4][4];
#pragma unroll
        for (int mt = 0; mt < 2; mt++)
#pragma unroll
            for (int nt = 0; nt < 4; nt++)
#pragma unroll
                for (int i = 0; i < 4; i++) acc[mt][nt][i] = 0.f;

        mma_3pass(acc, Ahi, Alo, Wh, Wl, aoff, boff);

        const int ntile = tile + gridDim.x;
        if (ntile < NT_TILES) prefetch_A(A, ntile * 128 + srow, sq, px);

        // epilogue: bias + relu + store
#pragma unroll
        for (int mt = 0; mt < 2; mt++) {
            int ra = row0 + wm * 32 + mt * 16 + g;
            int rb = ra + 8;
#pragma unroll
            for (int nt = 0; nt < 4; nt++) {
                int col = wn * 32 + nt * 8 + c2;
                if (ra < N_NODES)
                    *reinterpret_cast<float2*>(out + (size_t)ra * D + col) =
                        make_float2(fmaxf(acc[mt][nt][0] + sb[col], 0.f),
                                    fmaxf(acc[mt][nt][1] + sb[col + 1], 0.f));
                if (rb < N_NODES)
                    *reinterpret_cast<float2*>(out + (size_t)rb * D + col) =
                        make_float2(fmaxf(acc[mt][nt][2] + sb[col], 0.f),
                                    fmaxf(acc[mt][nt][3] + sb[col + 1], 0.f));
            }
        }
        __syncthreads();   // As reuse next tile
    }
}

// ---------------------------------------------------------------------------
__global__ void k_bnprep(const float* __restrict__ gamma,
                         const float* __restrict__ beta) {
    int t = threadIdx.x;
    float inv_n = 1.0f / (float)N_NODES;
    float mu = g_colsum[t] * inv_n;
    float var = g_colsq[t] * inv_n - mu * mu;
    float a = gamma[t] * rsqrtf(var + 1e-5f);
    g_bn[t] = a;
    g_bn[D + t] = beta[t] - mu * a;
}

// ---------------------------------------------------------------------------
__global__ void __launch_bounds__(256) k_pairs(const float* __restrict__ h,
                                               const int* __restrict__ pairs,
                                               const float* __restrict__ Wfc,
                                               const float* __restrict__ bfc,
                                               float* __restrict__ out) {
    __shared__ float sW[O_OUT][D];
    __shared__ float sb[O_OUT];
    int t = threadIdx.x;
    for (int i = t; i < O_OUT * D; i += 256) sW[i / D][i % D] = Wfc[i];
    if (t < O_OUT) sb[t] = bfc[t];
    __syncthreads();

    int p = (blockIdx.x * 256 + t) >> 5;
    int lane = t & 31;
    if (p >= P_PAIRS) return;

    int i0 = pairs[2 * p];
    int i1 = pairs[2 * p + 1];
    float4 u = reinterpret_cast<const float4*>(h + (size_t)i0 * D)[lane];
    float4 v = reinterpret_cast<const float4*>(h + (size_t)i1 * D)[lane];
    float4 w = make_float4(u.x * v.x, u.y * v.y, u.z * v.z, u.w * v.w);

    float s[O_OUT];
#pragma unroll
    for (int o = 0; o < O_OUT; o++)
        s[o] = w.x * sW[o][4 * lane + 0] + w.y * sW[o][4 * lane + 1] +
               w.z * sW[o][4 * lane + 2] + w.w * sW[o][4 * lane + 3];
#pragma unroll
    for (int o = 0; o < O_OUT; o++)
#pragma unroll
        for (int off = 16; off > 0; off >>= 1)
            s[o] += __shfl_xor_sync(0xffffffffu, s[o], off);
    if (lane == 0)
#pragma unroll
        for (int o = 0; o < O_OUT; o++) out[(size_t)p * O_OUT + o] = s[o] + sb[o];
}

// ---------------------------------------------------------------------------
extern "C" void kernel_launch(void* const* d_in, const int* in_sizes, int n_in,
                              void* d_out, int out_size) {
    const float* x    = (const float*)d_in[0];
    const float* W1a  = (const float*)d_in[1];
    const float* b1a  = (const float*)d_in[2];
    const float* W2a  = (const float*)d_in[3];
    const float* b2a  = (const float*)d_in[4];
    const float* g0   = (const float*)d_in[5];
    const float* bt0  = (const float*)d_in[6];
    const float* eps0 = (const float*)d_in[7];
    const float* W1b  = (const float*)d_in[8];
    const float* b1b  = (const float*)d_in[9];
    const float* W2b  = (const float*)d_in[10];
    const float* b2b  = (const float*)d_in[11];
    const float* g1   = (const float*)d_in[12];
    const float* bt1  = (const float*)d_in[13];
    const float* eps1 = (const float*)d_in[14];
    const float* Wl   = (const float*)d_in[15];
    const float* bl   = (const float*)d_in[16];
    const float* Wfc  = (const float*)d_in[17];
    const float* bfc  = (const float*)d_in[18];
    const int* esrc   = (const int*)d_in[19];
    const int* edst   = (const int*)d_in[20];
    const int* pairs  = (const int*)d_in[21];
    float* out = (float*)d_out;

    float *t, *h;
    __nv_bfloat16 *wh, *wl;
    cudaGetSymbolAddress((void**)&t, g_t);
    cudaGetSymbolAddress((void**)&h, g_h);
    cudaGetSymbolAddress((void**)&wh, g_wh);
    cudaGetSymbolAddress((void**)&wl, g_wl);

    cudaFuncSetAttribute(k_mlp<0>, cudaFuncAttributeMaxDynamicSharedMemorySize, SMEM_MLP);
    cudaFuncSetAttribute(k_mlp<1>, cudaFuncAttributeMaxDynamicSharedMemorySize, SMEM_MLP);
    cudaFuncSetAttribute(k_gemm_l, cudaFuncAttributeMaxDynamicSharedMemorySize, SMEM_GL);

    const int ZB = (N_NODES * D / 4 + 255) / 256;
    const int SB = (E_EDGES * 32 + 255) / 256;
    const int PB = (P_PAIRS * 32) / 256;
    const int WS = D * D;
    const int PG = 148;

    k_prep_w<<<(5 * WS + 255) / 256, 256>>>(W1a, W2a, W1b, W2b, Wl);

    // Layer A
    k_zero<<<ZB, 256>>>();
    k_scatter<0><<<SB, 256>>>(x, esrc, edst);
    k_mlp<0><<<PG, 512, SMEM_MLP>>>(x, eps0, b1a, b2a,
                                    wh + 0 * WS, wl + 0 * WS,
                                    wh + 1 * WS, wl + 1 * WS, h);
    k_bnprep<<<1, 128>>>(g0, bt0);

    // Layer B (BN-A affine folded into scatter + mlp stage)
    k_zero<<<ZB, 256>>>();
    k_scatter<1><<<SB, 256>>>(h, esrc, edst);
    k_mlp<1><<<PG, 512, SMEM_MLP>>>(h, eps1, b1b, b2b,
                                    wh + 2 * WS, wl + 2 * WS,
                                    wh + 3 * WS, wl + 3 * WS, h);
    k_bnprep<<<1, 128>>>(g1, bt1);

    // Final linear (BN-B affine folded) + pair head
    k_gemm_l<<<PG, 512, SMEM_GL>>>(h, bl, wh + 4 * WS, wl + 4 * WS, t);
    k_pairs<<<PB, 256>>>(t, pairs, Wfc, bfc, out);
}

// round 11
// speedup vs baseline: 2.1682x; 1.0107x over previous
#include <cuda_runtime.h>
#include <cuda_bf16.h>
#include <cstdint>

#define N_NODES 50000
#define D 128
#define E_EDGES 600000
#define P_PAIRS 131072
#define O_OUT 7
#define NT64 782                             // ceil(N/64)

#define HROW_U32 68                          // padded row: 272 B
#define HARR_U32 (64 * HROW_U32)             // 64-row bf16 array (A halves)
#define HARR_BYTES (HARR_U32 * 4)            // 17408
#define WARR_U32 (128 * HROW_U32)            // full 128-row weight array
#define WARR_BYTES (WARR_U32 * 4)            // 34816
#define SMEM_MLP (4 * HARR_BYTES + 4 * WARR_BYTES)   // 208896
#define SMEM_GL  (4 * HARR_BYTES + 2 * WARR_BYTES)   // 139264

// Scratch
__device__ float g_agg[N_NODES * D];
__device__ float g_t[N_NODES * D];
__device__ float g_h[N_NODES * D];
__device__ float g_colsum[D];
__device__ float g_colsq[D];
__device__ float g_bn[2 * D];                // [0:128) a, [128:256) c
__device__ __nv_bfloat16 g_wh[5 * D * D];    // dense pre-split weights (hi)
__device__ __nv_bfloat16 g_wl[5 * D * D];    // (lo residual)

// ---------------------------------------------------------------------------
__global__ void k_prep_w(const float* __restrict__ w0, const float* __restrict__ w1,
                         const float* __restrict__ w2, const float* __restrict__ w3,
                         const float* __restrict__ w4) {
    int i = blockIdx.x * blockDim.x + threadIdx.x;
    if (i >= 5 * D * D) return;
    const float* srcs[5] = {w0, w1, w2, w3, w4};
    float v = srcs[i >> 14][i & 16383];
    __nv_bfloat16 h = __float2bfloat16(v);
    g_wh[i] = h;
    g_wl[i] = __float2bfloat16(v - __bfloat162float(h));
}

__global__ void k_zero() {
    int i = blockIdx.x * blockDim.x + threadIdx.x;
    if (i < N_NODES * D / 4)
        reinterpret_cast<float4*>(g_agg)[i] = make_float4(0.f, 0.f, 0.f, 0.f);
    if (blockIdx.x == 0 && threadIdx.x < D) {
        g_colsum[threadIdx.x] = 0.f;
        g_colsq[threadIdx.x] = 0.f;
    }
}

// ---------------------------------------------------------------------------
// Edge scatter: agg[dst] += f(h[src]); AFF folds BN affine
// ---------------------------------------------------------------------------
template <int AFF>
__global__ void k_scatter(const float* __restrict__ h,
                          const int* __restrict__ src,
                          const int* __restrict__ dst) {
    int e = (blockIdx.x * blockDim.x + threadIdx.x) >> 5;
    int lane = threadIdx.x & 31;
    if (e >= E_EDGES) return;
    int s = src[e];
    int d = dst[e];
    float4 v = reinterpret_cast<const float4*>(h + (size_t)s * D)[lane];
    if (AFF) {
        float4 a = *reinterpret_cast<const float4*>(g_bn + lane * 4);
        float4 c = *reinterpret_cast<const float4*>(g_bn + D + lane * 4);
        v.x = a.x * v.x + c.x;
        v.y = a.y * v.y + c.y;
        v.z = a.z * v.z + c.z;
        v.w = a.w * v.w + c.w;
    }
    float* o = g_agg + (size_t)d * D + lane * 4;
    asm volatile("red.global.add.v4.f32 [%0], {%1,%2,%3,%4};"
                 :: "l"(o), "f"(v.x), "f"(v.y), "f"(v.z), "f"(v.w) : "memory");
}

// ---------------------------------------------------------------------------
// MMA helpers (ldmatrix: non-volatile + memory clobber; mma: pure register)
// ---------------------------------------------------------------------------
static __device__ __forceinline__ uint32_t smem_u32(const void* p) {
    return (uint32_t)__cvta_generic_to_shared(p);
}
static __device__ __forceinline__ void split2(float a, float b, uint32_t& hi, uint32_t& lo) {
    __nv_bfloat162 h = __floats2bfloat162_rn(a, b);
    float ra = a - __bfloat162float(h.x);
    float rb = b - __bfloat162float(h.y);
    __nv_bfloat162 l = __floats2bfloat162_rn(ra, rb);
    hi = *reinterpret_cast<uint32_t*>(&h);
    lo = *reinterpret_cast<uint32_t*>(&l);
}
static __device__ __forceinline__ void ldmx4(uint32_t addr, uint32_t r[4]) {
    asm("ldmatrix.sync.aligned.m8n8.x4.shared.b16 {%0,%1,%2,%3}, [%4];"
        : "=r"(r[0]), "=r"(r[1]), "=r"(r[2]), "=r"(r[3]) : "r"(addr) : "memory");
}
static __device__ __forceinline__ void mma16816(float c[4], const uint32_t a[4],
                                                uint32_t b0, uint32_t b1) {
    asm("mma.sync.aligned.m16n8k16.row.col.f32.bf16.bf16.f32 "
        "{%0,%1,%2,%3},{%4,%5,%6,%7},{%8,%9},{%0,%1,%2,%3};"
        : "+f"(c[0]), "+f"(c[1]), "+f"(c[2]), "+f"(c[3])
        : "r"(a[0]), "r"(a[1]), "r"(a[2]), "r"(a[3]), "r"(b0), "r"(b1));
}
static __device__ __forceinline__ void cpa16(uint32_t dst, const void* src) {
    asm volatile("cp.async.cg.shared.global [%0], [%1], 16;"
                 :: "r"(dst), "l"(src) : "memory");
}
static __device__ __forceinline__ void barg(int id) {
    asm volatile("bar.sync %0, 256;" :: "r"(id) : "memory");
}

// 3-pass GEMM body (hi*hi + hi*lo + lo*hi), pass-major order; warp tile 32x32
static __device__ __forceinline__ void mma_3pass(float acc[2][4][4],
                                                 uint32_t Ahi, uint32_t Alo,
                                                 uint32_t Bhi, uint32_t Blo,
                                                 const uint32_t aoff[2],
                                                 const uint32_t boff[2]) {
#pragma unroll
    for (int ks = 0; ks < 8; ks++) {
        uint32_t kb = ks * 32;
        uint32_t ah[2][4], al[2][4], bh[2][4], bl[2][4];
#pragma unroll
        for (int mt = 0; mt < 2; mt++) {
            ldmx4(Ahi + aoff[mt] + kb, ah[mt]);
            ldmx4(Alo + aoff[mt] + kb, al[mt]);
        }
#pragma unroll
        for (int np = 0; np < 2; np++) {
            ldmx4(Bhi + boff[np] + kb, bh[np]);
            ldmx4(Blo + boff[np] + kb, bl[np]);
        }
#pragma unroll
        for (int mt = 0; mt < 2; mt++)
#pragma unroll
            for (int nt = 0; nt < 4; nt++) {
                int np = nt >> 1, o = (nt & 1) * 2;
                mma16816(acc[mt][nt], ah[mt], bh[np][o], bh[np][o + 1]);
            }
#pragma unroll
        for (int mt = 0; mt < 2; mt++)
#pragma unroll
            for (int nt = 0; nt < 4; nt++) {
                int np = nt >> 1, o = (nt & 1) * 2;
                mma16816(acc[mt][nt], ah[mt], bl[np][o], bl[np][o + 1]);
            }
#pragma unroll
        for (int mt = 0; mt < 2; mt++)
#pragma unroll
            for (int nt = 0; nt < 4; nt++) {
                int np = nt >> 1, o = (nt & 1) * 2;
                mma16816(acc[mt][nt], al[mt], bh[np][o], bh[np][o + 1]);
            }
    }
}

// cp.async one dense 128x128 bf16 weight array into padded smem (512 thr)
static __device__ __forceinline__ void stage_W(const __nv_bfloat16* __restrict__ w,
                                               uint32_t dbase, int t) {
#pragma unroll
    for (int it = 0; it < 4; it++) {
        int c = t + it * 512;                 // 0..2047
        int row = c >> 4, j = c & 15;
        cpa16(dbase + row * 272 + j * 16, w + row * D + j * 8);
    }
}

// prefetch one 64-row tile's A rows into registers (8 float4 per thread/group)
static __device__ __forceinline__ void prefetch_A(const float* __restrict__ A,
                                                  int gr, int sq, float4 px[8]) {
    if (gr < N_NODES) {
        const float4* Ar = reinterpret_cast<const float4*>(A + (size_t)gr * D);
#pragma unroll
        for (int j = 0; j < 8; j++) px[j] = Ar[sq * 8 + j];
    }
}

// ---------------------------------------------------------------------------
// Persistent fused GIN MLP: 2 independent 256-thread groups per CTA, each on
// its own 64-row tile stream with its own A buffers; weights shared.
// ---------------------------------------------------------------------------
template <int AFF>
__global__ void __launch_bounds__(512) k_mlp(const float* __restrict__ A,
                                             const float* __restrict__ epsp,
                                             const float* __restrict__ b1,
                                             const float* __restrict__ b2,
                                             const __nv_bfloat16* __restrict__ w1h,
                                             const __nv_bfloat16* __restrict__ w1l,
                                             const __nv_bfloat16* __restrict__ w2h,
                                             const __nv_bfloat16* __restrict__ w2l,
                                             float* __restrict__ out) {
    extern __shared__ uint32_t smem[];
    __shared__ float sb1[D], sb2[D], s_sum[D], s_sq[D];

    const int t = threadIdx.x;
    const int grp = t >> 8;                  // 0 or 1
    const int t2 = t & 255;
    const int warp8 = t2 >> 5, lane = t & 31;
    const int wm = warp8 & 1, wn = warp8 >> 1;   // 2M x 4N (64 x 128)
    const float cA = 1.0f + *epsp;

    uint32_t* As_hi = smem + grp * 2 * HARR_U32;
    uint32_t* As_lo = As_hi + HARR_U32;
    uint32_t* wbase = smem + 4 * HARR_U32;

    if (t < D) {
        sb1[t] = __ldg(b1 + t);
        sb2[t] = __ldg(b2 + t);
        s_sum[t] = 0.f;
        s_sq[t] = 0.f;
    }

    const uint32_t W1h = smem_u32(wbase);
    const uint32_t W1l = smem_u32(wbase + WARR_U32 * 1);
    const uint32_t W2h = smem_u32(wbase + WARR_U32 * 2);
    const uint32_t W2l = smem_u32(wbase + WARR_U32 * 3);
    stage_W(w1h, W1h, t);
    stage_W(w1l, W1l, t);
    stage_W(w2h, W2h, t);
    stage_W(w2l, W2l, t);
    asm volatile("cp.async.commit_group;" ::: "memory");

    uint32_t aoff[2], boff[2];
#pragma unroll
    for (int mt = 0; mt < 2; mt++) {
        int row = wm * 32 + mt * 16 + ((lane >> 3) & 1) * 8 + (lane & 7);
        aoff[mt] = row * 272 + (lane >> 4) * 16;
    }
#pragma unroll
    for (int np = 0; np < 2; np++) {
        int row = wn * 32 + np * 16 + (lane >> 4) * 8 + (lane & 7);
        boff[np] = row * 272 + ((lane >> 3) & 1) * 16;
    }
    const uint32_t Ahi = smem_u32(As_hi), Alo = smem_u32(As_lo);
    const int lg = lane >> 2;                // row-in-8 group
    const int c2 = (lane & 3) * 2;
    const int srow = t2 >> 2, sq = t2 & 3;   // staging: 4 thr/row, 64 rows
    const int bid = 1 + grp;                 // named barrier id

    // prologue
    int tile = blockIdx.x * 2 + grp;
    const int step = gridDim.x * 2;
    float4 px[8];
    prefetch_A(A, tile * 64 + srow, sq, px);
    asm volatile("cp.async.wait_group 0;" ::: "memory");
    __syncthreads();

    for (; tile < NT64; tile += step) {
        const int row0 = tile * 64;
        const int gr = row0 + srow;

        // stage current tile from registers (+agg +affine +combine)
        {
            const float4* Gr = reinterpret_cast<const float4*>(g_agg + (size_t)gr * D);
#pragma unroll
            for (int j = 0; j < 8; j++) {
                int f4 = sq * 8 + j;
                float4 v = make_float4(0.f, 0.f, 0.f, 0.f);
                if (gr < N_NODES) {
                    v = px[j];
                    if (AFF) {
                        float4 a = *reinterpret_cast<const float4*>(g_bn + f4 * 4);
                        float4 c = *reinterpret_cast<const float4*>(g_bn + D + f4 * 4);
                        v.x = a.x * v.x + c.x; v.y = a.y * v.y + c.y;
                        v.z = a.z * v.z + c.z; v.w = a.w * v.w + c.w;
                    }
                    float4 q4 = Gr[f4];
                    v.x = cA * v.x + q4.x; v.y = cA * v.y + q4.y;
                    v.z = cA * v.z + q4.z; v.w = cA * v.w + q4.w;
                }
                uint32_t h0, l0, h1, l1;
                split2(v.x, v.y, h0, l0);
                split2(v.z, v.w, h1, l1);
                int o = srow * HROW_U32 + f4 * 2;
                *reinterpret_cast<uint2*>(&As_hi[o]) = make_uint2(h0, h1);
                *reinterpret_cast<uint2*>(&As_lo[o]) = make_uint2(l0, l1);
            }
        }
        barg(bid);

        float acc[2][4][4];
#pragma unroll
        for (int mt = 0; mt < 2; mt++)
#pragma unroll
            for (int nt = 0; nt < 4; nt++)
#pragma unroll
                for (int i = 0; i < 4; i++) acc[mt][nt][i] = 0.f;

        // ---- GEMM1 ----
        mma_3pass(acc, Ahi, Alo, W1h, W1l, aoff, boff);

        // prefetch next tile
        const int ntile = tile + step;
        if (ntile < NT64) prefetch_A(A, ntile * 64 + srow, sq, px);

        barg(bid);   // GEMM1 reads of As done

        // epilogue1: P = relu(acc+b1) -> bf16 hi/lo back into As
#pragma unroll
        for (int mt = 0; mt < 2; mt++) {
            int ra = wm * 32 + mt * 16 + lg;
            int rb = ra + 8;
#pragma unroll
            for (int nt = 0; nt < 4; nt++) {
                int col = wn * 32 + nt * 8 + c2;
                int o = col >> 1;
                float t0 = fmaxf(acc[mt][nt][0] + sb1[col], 0.f);
                float t1 = fmaxf(acc[mt][nt][1] + sb1[col + 1], 0.f);
                float t2v = fmaxf(acc[mt][nt][2] + sb1[col], 0.f);
                float t3 = fmaxf(acc[mt][nt][3] + sb1[col + 1], 0.f);
                uint32_t hi, lo;
                split2(t0, t1, hi, lo);
                As_hi[ra * HROW_U32 + o] = hi;
                As_lo[ra * HROW_U32 + o] = lo;
                split2(t2v, t3, hi, lo);
                As_hi[rb * HROW_U32 + o] = hi;
                As_lo[rb * HROW_U32 + o] = lo;
#pragma unroll
                for (int i = 0; i < 4; i++) acc[mt][nt][i] = 0.f;
            }
        }
        barg(bid);   // P staged

        // ---- GEMM2 ----
        mma_3pass(acc, Ahi, Alo, W2h, W2l, aoff, boff);
        barg(bid);   // GEMM2 reads done -> next stage may overwrite As

        // epilogue2: relu+bias, store h, accumulate column stats
        {
            float sp[4][2], qp[4][2];
#pragma unroll
            for (int nt = 0; nt < 4; nt++) {
                sp[nt][0] = sp[nt][1] = 0.f;
                qp[nt][0] = qp[nt][1] = 0.f;
            }
#pragma unroll
            for (int mt = 0; mt < 2; mt++) {
                int ra = row0 + wm * 32 + mt * 16 + lg;
                int rb = ra + 8;
#pragma unroll
                for (int nt = 0; nt < 4; nt++) {
                    int col = wn * 32 + nt * 8 + c2;
                    float v0 = fmaxf(acc[mt][nt][0] + sb2[col], 0.f);
                    float v1 = fmaxf(acc[mt][nt][1] + sb2[col + 1], 0.f);
                    float v2 = fmaxf(acc[mt][nt][2] + sb2[col], 0.f);
                    float v3 = fmaxf(acc[mt][nt][3] + sb2[col + 1], 0.f);
                    if (ra < N_NODES) {
                        *reinterpret_cast<float2*>(out + (size_t)ra * D + col) =
                            make_float2(v0, v1);
                        sp[nt][0] += v0; sp[nt][1] += v1;
                        qp[nt][0] += v0 * v0; qp[nt][1] += v1 * v1;
                    }
                    if (rb < N_NODES) {
                        *reinterpret_cast<float2*>(out + (size_t)rb * D + col) =
                            make_float2(v2, v3);
                        sp[nt][0] += v2; sp[nt][1] += v3;
                        qp[nt][0] += v2 * v2; qp[nt][1] += v3 * v3;
                    }
                }
            }
#pragma unroll
            for (int nt = 0; nt < 4; nt++) {
#pragma unroll
                for (int d = 4; d < 32; d <<= 1) {
                    sp[nt][0] += __shfl_xor_sync(0xffffffffu, sp[nt][0], d);
                    sp[nt][1] += __shfl_xor_sync(0xffffffffu, sp[nt][1], d);
                    qp[nt][0] += __shfl_xor_sync(0xffffffffu, qp[nt][0], d);
                    qp[nt][1] += __shfl_xor_sync(0xffffffffu, qp[nt][1], d);
                }
            }
            if (lg == 0) {
#pragma unroll
                for (int nt = 0; nt < 4; nt++) {
                    int col = wn * 32 + nt * 8 + c2;
                    atomicAdd(&s_sum[col], sp[nt][0]);
                    atomicAdd(&s_sum[col + 1], sp[nt][1]);
                    atomicAdd(&s_sq[col], qp[nt][0]);
                    atomicAdd(&s_sq[col + 1], qp[nt][1]);
                }
            }
        }
    }

    __syncthreads();
    if (t < D) {
        asm volatile("red.global.add.f32 [%0], %1;" :: "l"(&g_colsum[t]), "f"(s_sum[t]) : "memory");
        asm volatile("red.global.add.f32 [%0], %1;" :: "l"(&g_colsq[t]), "f"(s_sq[t]) : "memory");
    }
}

// ---------------------------------------------------------------------------
// Persistent final linear, dual-group: t = relu((a*h+c) @ Wl^T + bl)
// ---------------------------------------------------------------------------
__global__ void __launch_bounds__(512) k_gemm_l(const float* __restrict__ A,
                                                const float* __restrict__ bias,
                                                const __nv_bfloat16* __restrict__ wh,
                                                const __nv_bfloat16* __restrict__ wl,
                                                float* __restrict__ out) {
    extern __shared__ uint32_t smem[];
    __shared__ float sb[D];

    const int t = threadIdx.x;
    const int grp = t >> 8;
    const int t2 = t & 255;
    const int warp8 = t2 >> 5, lane = t & 31;
    const int wm = warp8 & 1, wn = warp8 >> 1;

    uint32_t* As_hi = smem + grp * 2 * HARR_U32;
    uint32_t* As_lo = As_hi + HARR_U32;
    uint32_t* wbase = smem + 4 * HARR_U32;

    if (t < D) sb[t] = __ldg(bias + t);

    const uint32_t Wh = smem_u32(wbase);
    const uint32_t Wl = smem_u32(wbase + WARR_U32);
    stage_W(wh, Wh, t);
    stage_W(wl, Wl, t);
    asm volatile("cp.async.commit_group;" ::: "memory");

    uint32_t aoff[2], boff[2];
#pragma unroll
    for (int mt = 0; mt < 2; mt++) {
        int row = wm * 32 + mt * 16 + ((lane >> 3) & 1) * 8 + (lane & 7);
        aoff[mt] = row * 272 + (lane >> 4) * 16;
    }
#pragma unroll
    for (int np = 0; np < 2; np++) {
        int row = wn * 32 + np * 16 + (lane >> 4) * 8 + (lane & 7);
        boff[np] = row * 272 + ((lane >> 3) & 1) * 16;
    }
    const uint32_t Ahi = smem_u32(As_hi), Alo = smem_u32(As_lo);
    const int lg = lane >> 2;
    const int c2 = (lane & 3) * 2;
    const int srow = t2 >> 2, sq = t2 & 3;
    const int bid = 1 + grp;

    int tile = blockIdx.x * 2 + grp;
    const int step = gridDim.x * 2;
    float4 px[8];
    prefetch_A(A, tile * 64 + srow, sq, px);
    asm volatile("cp.async.wait_group 0;" ::: "memory");
    __syncthreads();

    for (; tile < NT64; tile += step) {
        const int row0 = tile * 64;
        const int gr = row0 + srow;

        // stage current tile from registers (+BN affine)
#pragma unroll
        for (int j = 0; j < 8; j++) {
            int f4 = sq * 8 + j;
            float4 v = make_float4(0.f, 0.f, 0.f, 0.f);
            if (gr < N_NODES) {
                v = px[j];
                float4 a = *reinterpret_cast<const float4*>(g_bn + f4 * 4);
                float4 c = *reinterpret_cast<const float4*>(g_bn + D + f4 * 4);
                v.x = a.x * v.x + c.x; v.y = a.y * v.y + c.y;
                v.z = a.z * v.z + c.z; v.w = a.w * v.w + c.w;
            }
            uint32_t h0, l0, h1, l1;
            split2(v.x, v.y, h0, l0);
            split2(v.z, v.w, h1, l1);
            int o = srow * HROW_U32 + f4 * 2;
            *reinterpret_cast<uint2*>(&As_hi[o]) = make_uint2(h0, h1);
            *reinterpret_cast<uint2*>(&As_lo[o]) = make_uint2(l0, l1);
        }
        barg(bid);

        float acc[2][4][4];
#pragma unroll
        for (int mt = 0; mt < 2; mt++)
#pragma unroll
            for (int nt = 0; nt < 4; nt++)
#pragma unroll
                for (int i = 0; i < 4; i++) acc[mt][nt][i] = 0.f;

        mma_3pass(acc, Ahi, Alo, Wh, Wl, aoff, boff);

        const int ntile = tile + step;
        if (ntile < NT64) prefetch_A(A, ntile * 64 + srow, sq, px);

        barg(bid);   // GEMM reads done -> next stage may overwrite

        // epilogue: bias + relu + store (registers only, no As access)
#pragma unroll
        for (int mt = 0; mt < 2; mt++) {
            int ra = row0 + wm * 32 + mt * 16 + lg;
            int rb = ra + 8;
#pragma unroll
            for (int nt = 0; nt < 4; nt++) {
                int col = wn * 32 + nt * 8 + c2;
                if (ra < N_NODES)
                    *reinterpret_cast<float2*>(out + (size_t)ra * D + col) =
                        make_float2(fmaxf(acc[mt][nt][0] + sb[col], 0.f),
                                    fmaxf(acc[mt][nt][1] + sb[col + 1], 0.f));
                if (rb < N_NODES)
                    *reinterpret_cast<float2*>(out + (size_t)rb * D + col) =
                        make_float2(fmaxf(acc[mt][nt][2] + sb[col], 0.f),
                                    fmaxf(acc[mt][nt][3] + sb[col + 1], 0.f));
            }
        }
    }
}

// ---------------------------------------------------------------------------
__global__ void k_bnprep(const float* __restrict__ gamma,
                         const float* __restrict__ beta) {
    int t = threadIdx.x;
    float inv_n = 1.0f / (float)N_NODES;
    float mu = g_colsum[t] * inv_n;
    float var = g_colsq[t] * inv_n - mu * mu;
    float a = gamma[t] * rsqrtf(var + 1e-5f);
    g_bn[t] = a;
    g_bn[D + t] = beta[t] - mu * a;
}

// ---------------------------------------------------------------------------
__global__ void __launch_bounds__(256) k_pairs(const float* __restrict__ h,
                                               const int* __restrict__ pairs,
                                               const float* __restrict__ Wfc,
                                               const float* __restrict__ bfc,
                                               float* __restrict__ out) {
    __shared__ float sW[O_OUT][D];
    __shared__ float sb[O_OUT];
    int t = threadIdx.x;
    for (int i = t; i < O_OUT * D; i += 256) sW[i / D][i % D] = Wfc[i];
    if (t < O_OUT) sb[t] = bfc[t];
    __syncthreads();

    int p = (blockIdx.x * 256 + t) >> 5;
    int lane = t & 31;
    if (p >= P_PAIRS) return;

    int i0 = pairs[2 * p];
    int i1 = pairs[2 * p + 1];
    float4 u = reinterpret_cast<const float4*>(h + (size_t)i0 * D)[lane];
    float4 v = reinterpret_cast<const float4*>(h + (size_t)i1 * D)[lane];
    float4 w = make_float4(u.x * v.x, u.y * v.y, u.z * v.z, u.w * v.w);

    float s[O_OUT];
#pragma unroll
    for (int o = 0; o < O_OUT; o++)
        s[o] = w.x * sW[o][4 * lane + 0] + w.y * sW[o][4 * lane + 1] +
               w.z * sW[o][4 * lane + 2] + w.w * sW[o][4 * lane + 3];
#pragma unroll
    for (int o = 0; o < O_OUT; o++)
#pragma unroll
        for (int off = 16; off > 0; off >>= 1)
            s[o] += __shfl_xor_sync(0xffffffffu, s[o], off);
    if (lane == 0)
#pragma unroll
        for (int o = 0; o < O_OUT; o++) out[(size_t)p * O_OUT + o] = s[o] + sb[o];
}

// ---------------------------------------------------------------------------
extern "C" void kernel_launch(void* const* d_in, const int* in_sizes, int n_in,
                              void* d_out, int out_size) {
    const float* x    = (const float*)d_in[0];
    const float* W1a  = (const float*)d_in[1];
    const float* b1a  = (const float*)d_in[2];
    const float* W2a  = (const float*)d_in[3];
    const float* b2a  = (const float*)d_in[4];
    const float* g0   = (const float*)d_in[5];
    const float* bt0  = (const float*)d_in[6];
    const float* eps0 = (const float*)d_in[7];
    const float* W1b  = (const float*)d_in[8];
    const float* b1b  = (const float*)d_in[9];
    const float* W2b  = (const float*)d_in[10];
    const float* b2b  = (const float*)d_in[11];
    const float* g1   = (const float*)d_in[12];
    const float* bt1  = (const float*)d_in[13];
    const float* eps1 = (const float*)d_in[14];
    const float* Wl   = (const float*)d_in[15];
    const float* bl   = (const float*)d_in[16];
    const float* Wfc  = (const float*)d_in[17];
    const float* bfc  = (const float*)d_in[18];
    const int* esrc   = (const int*)d_in[19];
    const int* edst   = (const int*)d_in[20];
    const int* pairs  = (const int*)d_in[21];
    float* out = (float*)d_out;

    float *t, *h;
    __nv_bfloat16 *wh, *wl;
    cudaGetSymbolAddress((void**)&t, g_t);
    cudaGetSymbolAddress((void**)&h, g_h);
    cudaGetSymbolAddress((void**)&wh, g_wh);
    cudaGetSymbolAddress((void**)&wl, g_wl);

    cudaFuncSetAttribute(k_mlp<0>, cudaFuncAttributeMaxDynamicSharedMemorySize, SMEM_MLP);
    cudaFuncSetAttribute(k_mlp<1>, cudaFuncAttributeMaxDynamicSharedMemorySize, SMEM_MLP);
    cudaFuncSetAttribute(k_gemm_l, cudaFuncAttributeMaxDynamicSharedMemorySize, SMEM_GL);

    const int ZB = (N_NODES * D / 4 + 255) / 256;
    const int SB = (E_EDGES * 32 + 255) / 256;
    const int PB = (P_PAIRS * 32) / 256;
    const int WS = D * D;
    const int PG = 148;

    k_prep_w<<<(5 * WS + 255) / 256, 256>>>(W1a, W2a, W1b, W2b, Wl);

    // Layer A
    k_zero<<<ZB, 256>>>();
    k_scatter<0><<<SB, 256>>>(x, esrc, edst);
    k_mlp<0><<<PG, 512, SMEM_MLP>>>(x, eps0, b1a, b2a,
                                    wh + 0 * WS, wl + 0 * WS,
                                    wh + 1 * WS, wl + 1 * WS, h);
    k_bnprep<<<1, 128>>>(g0, bt0);

    // Layer B (BN-A affine folded into scatter + mlp stage)
    k_zero<<<ZB, 256>>>();
    k_scatter<1><<<SB, 256>>>(h, esrc, edst);
    k_mlp<1><<<PG, 512, SMEM_MLP>>>(h, eps1, b1b, b2b,
                                    wh + 2 * WS, wl + 2 * WS,
                                    wh + 3 * WS, wl + 3 * WS, h);
    k_bnprep<<<1, 128>>>(g1, bt1);

    // Final linear (BN-B affine folded) + pair head
    k_gemm_l<<<PG, 512, SMEM_GL>>>(h, bl, wh + 4 * WS, wl + 4 * WS, t);
    k_pairs<<<PB, 256>>>(t, pairs, Wfc, bfc, out);
}

// round 12
// speedup vs baseline: 2.1989x; 1.0142x over previous
#include <cuda_runtime.h>
#include <cuda_bf16.h>
#include <cstdint>

#define N_NODES 50000
#define E_EDGES 600000
#define D 128
#define P_PAIRS 131072
#define O_OUT 7
#define NT64 782                             // ceil(N/64)

#define HROW_U32 68
#define HARR_U32 (64 * HROW_U32)
#define HARR_BYTES (HARR_U32 * 4)
#define WARR_U32 (128 * HROW_U32)
#define WARR_BYTES (WARR_U32 * 4)
#define SMEM_MLP (4 * HARR_BYTES + 4 * WARR_BYTES)
#define SMEM_GL  (4 * HARR_BYTES + 2 * WARR_BYTES)

// Scratch
__device__ float g_agg[N_NODES * D];
__device__ float g_t[N_NODES * D];
__device__ float g_h[N_NODES * D];
__device__ float g_colsum[D];
__device__ float g_colsq[D];
__device__ float g_bn[2 * D];
__device__ __nv_bfloat16 g_wh[5 * D * D];
__device__ __nv_bfloat16 g_wl[5 * D * D];
// CSR (rebuilt every launch)
__device__ int g_deg[N_NODES];
__device__ int g_off[N_NODES + 1];
__device__ int g_cur[N_NODES];
__device__ int g_elist[E_EDGES];

// ---------------------------------------------------------------------------
// prep: split weights; zero deg + stats (start of every launch)
// ---------------------------------------------------------------------------
__global__ void k_prep_w(const float* __restrict__ w0, const float* __restrict__ w1,
                         const float* __restrict__ w2, const float* __restrict__ w3,
                         const float* __restrict__ w4) {
    int i = blockIdx.x * blockDim.x + threadIdx.x;
    if (i < N_NODES) g_deg[i] = 0;
    if (i < D) { g_colsum[i] = 0.f; g_colsq[i] = 0.f; }
    if (i >= 5 * D * D) return;
    const float* srcs[5] = {w0, w1, w2, w3, w4};
    float v = srcs[i >> 14][i & 16383];
    __nv_bfloat16 h = __float2bfloat16(v);
    g_wh[i] = h;
    g_wl[i] = __float2bfloat16(v - __bfloat162float(h));
}

__global__ void k_hist(const int* __restrict__ dst) {
    int e = blockIdx.x * blockDim.x + threadIdx.x;
    if (e < E_EDGES) atomicAdd(&g_deg[dst[e]], 1);
}

// single block, 1024 threads: exclusive scan of g_deg -> g_off, g_cur
__global__ void __launch_bounds__(1024) k_scan() {
    __shared__ int s_tot[1024];
    const int CH = (N_NODES + 1023) / 1024;    // 49
    int t = threadIdx.x;
    int base = t * CH;
    int sum = 0;
    for (int i = 0; i < CH; i++) {
        int idx = base + i;
        if (idx < N_NODES) sum += g_deg[idx];
    }
    s_tot[t] = sum;
    __syncthreads();
    for (int off = 1; off < 1024; off <<= 1) {
        int v = 0;
        if (t >= off) v = s_tot[t - off];
        __syncthreads();
        if (t >= off) s_tot[t] += v;
        __syncthreads();
    }
    int run = (t == 0) ? 0 : s_tot[t - 1];
    for (int i = 0; i < CH; i++) {
        int idx = base + i;
        if (idx < N_NODES) {
            g_off[idx] = run;
            g_cur[idx] = run;
            run += g_deg[idx];
        }
    }
    if (t == 1023) g_off[N_NODES] = s_tot[1023];
}

__global__ void k_fill(const int* __restrict__ src, const int* __restrict__ dst) {
    int e = blockIdx.x * blockDim.x + threadIdx.x;
    if (e >= E_EDGES) return;
    int pos = atomicAdd(&g_cur[dst[e]], 1);
    g_elist[pos] = src[e];
}

// ---------------------------------------------------------------------------
// Gather: agg[d] = sum_{s in N(d)} h[s]; AFF: a*sum + deg*c. Warp per node.
// ---------------------------------------------------------------------------
template <int AFF>
__global__ void __launch_bounds__(256) k_gather(const float* __restrict__ h) {
    int d = (blockIdx.x * blockDim.x + threadIdx.x) >> 5;
    int lane = threadIdx.x & 31;
    if (d >= N_NODES) return;
    int beg = g_off[d], end = g_off[d + 1];
    float4 acc = make_float4(0.f, 0.f, 0.f, 0.f);
    for (int i = beg; i < end; i++) {
        int s = g_elist[i];
        float4 v = reinterpret_cast<const float4*>(h + (size_t)s * D)[lane];
        acc.x += v.x; acc.y += v.y; acc.z += v.z; acc.w += v.w;
    }
    if (AFF) {
        float deg = (float)(end - beg);
        float4 a = *reinterpret_cast<const float4*>(g_bn + lane * 4);
        float4 c = *reinterpret_cast<const float4*>(g_bn + D + lane * 4);
        acc.x = a.x * acc.x + deg * c.x;
        acc.y = a.y * acc.y + deg * c.y;
        acc.z = a.z * acc.z + deg * c.z;
        acc.w = a.w * acc.w + deg * c.w;
    }
    reinterpret_cast<float4*>(g_agg + (size_t)d * D)[lane] = acc;
}

// ---------------------------------------------------------------------------
// MMA helpers
// ---------------------------------------------------------------------------
static __device__ __forceinline__ uint32_t smem_u32(const void* p) {
    return (uint32_t)__cvta_generic_to_shared(p);
}
static __device__ __forceinline__ void split2(float a, float b, uint32_t& hi, uint32_t& lo) {
    __nv_bfloat162 h = __floats2bfloat162_rn(a, b);
    float ra = a - __bfloat162float(h.x);
    float rb = b - __bfloat162float(h.y);
    __nv_bfloat162 l = __floats2bfloat162_rn(ra, rb);
    hi = *reinterpret_cast<uint32_t*>(&h);
    lo = *reinterpret_cast<uint32_t*>(&l);
}
static __device__ __forceinline__ void ldmx4(uint32_t addr, uint32_t r[4]) {
    asm("ldmatrix.sync.aligned.m8n8.x4.shared.b16 {%0,%1,%2,%3}, [%4];"
        : "=r"(r[0]), "=r"(r[1]), "=r"(r[2]), "=r"(r[3]) : "r"(addr) : "memory");
}
static __device__ __forceinline__ void mma16816(float c[4], const uint32_t a[4],
                                                uint32_t b0, uint32_t b1) {
    asm("mma.sync.aligned.m16n8k16.row.col.f32.bf16.bf16.f32 "
        "{%0,%1,%2,%3},{%4,%5,%6,%7},{%8,%9},{%0,%1,%2,%3};"
        : "+f"(c[0]), "+f"(c[1]), "+f"(c[2]), "+f"(c[3])
        : "r"(a[0]), "r"(a[1]), "r"(a[2]), "r"(a[3]), "r"(b0), "r"(b1));
}
static __device__ __forceinline__ void cpa16(uint32_t dst, const void* src) {
    asm volatile("cp.async.cg.shared.global [%0], [%1], 16;"
                 :: "r"(dst), "l"(src) : "memory");
}
static __device__ __forceinline__ void barg(int id) {
    asm volatile("bar.sync %0, 256;" :: "r"(id) : "memory");
}

static __device__ __forceinline__ void mma_3pass(float acc[2][4][4],
                                                 uint32_t Ahi, uint32_t Alo,
                                                 uint32_t Bhi, uint32_t Blo,
                                                 const uint32_t aoff[2],
                                                 const uint32_t boff[2]) {
#pragma unroll
    for (int ks = 0; ks < 8; ks++) {
        uint32_t kb = ks * 32;
        uint32_t ah[2][4], al[2][4], bh[2][4], bl[2][4];
#pragma unroll
        for (int mt = 0; mt < 2; mt++) {
            ldmx4(Ahi + aoff[mt] + kb, ah[mt]);
            ldmx4(Alo + aoff[mt] + kb, al[mt]);
        }
#pragma unroll
        for (int np = 0; np < 2; np++) {
            ldmx4(Bhi + boff[np] + kb, bh[np]);
            ldmx4(Blo + boff[np] + kb, bl[np]);
        }
#pragma unroll
        for (int mt = 0; mt < 2; mt++)
#pragma unroll
            for (int nt = 0; nt < 4; nt++) {
                int np = nt >> 1, o = (nt & 1) * 2;
                mma16816(acc[mt][nt], ah[mt], bh[np][o], bh[np][o + 1]);
            }
#pragma unroll
        for (int mt = 0; mt < 2; mt++)
#pragma unroll
            for (int nt = 0; nt < 4; nt++) {
                int np = nt >> 1, o = (nt & 1) * 2;
                mma16816(acc[mt][nt], ah[mt], bl[np][o], bl[np][o + 1]);
            }
#pragma unroll
        for (int mt = 0; mt < 2; mt++)
#pragma unroll
            for (int nt = 0; nt < 4; nt++) {
                int np = nt >> 1, o = (nt & 1) * 2;
                mma16816(acc[mt][nt], al[mt], bh[np][o], bh[np][o + 1]);
            }
    }
}

static __device__ __forceinline__ void stage_W(const __nv_bfloat16* __restrict__ w,
                                               uint32_t dbase, int t) {
#pragma unroll
    for (int it = 0; it < 4; it++) {
        int c = t + it * 512;
        int row = c >> 4, j = c & 15;
        cpa16(dbase + row * 272 + j * 16, w + row * D + j * 8);
    }
}

static __device__ __forceinline__ void prefetch_A(const float* __restrict__ A,
                                                  int gr, int sq, float4 px[8]) {
    if (gr < N_NODES) {
        const float4* Ar = reinterpret_cast<const float4*>(A + (size_t)gr * D);
#pragma unroll
        for (int j = 0; j < 8; j++) px[j] = Ar[sq * 8 + j];
    }
}

// ---------------------------------------------------------------------------
// Persistent fused GIN MLP: 2 independent 256-thread groups per CTA
// ---------------------------------------------------------------------------
template <int AFF>
__global__ void __launch_bounds__(512) k_mlp(const float* __restrict__ A,
                                             const float* __restrict__ epsp,
                                             const float* __restrict__ b1,
                                             const float* __restrict__ b2,
                                             const __nv_bfloat16* __restrict__ w1h,
                                             const __nv_bfloat16* __restrict__ w1l,
                                             const __nv_bfloat16* __restrict__ w2h,
                                             const __nv_bfloat16* __restrict__ w2l,
                                             float* __restrict__ out) {
    extern __shared__ uint32_t smem[];
    __shared__ float sb1[D], sb2[D], s_sum[D], s_sq[D];

    const int t = threadIdx.x;
    const int grp = t >> 8;
    const int t2 = t & 255;
    const int warp8 = t2 >> 5, lane = t & 31;
    const int wm = warp8 & 1, wn = warp8 >> 1;
    const float cA = 1.0f + *epsp;

    uint32_t* As_hi = smem + grp * 2 * HARR_U32;
    uint32_t* As_lo = As_hi + HARR_U32;
    uint32_t* wbase = smem + 4 * HARR_U32;

    if (t < D) {
        sb1[t] = __ldg(b1 + t);
        sb2[t] = __ldg(b2 + t);
        s_sum[t] = 0.f;
        s_sq[t] = 0.f;
    }

    const uint32_t W1h = smem_u32(wbase);
    const uint32_t W1l = smem_u32(wbase + WARR_U32 * 1);
    const uint32_t W2h = smem_u32(wbase + WARR_U32 * 2);
    const uint32_t W2l = smem_u32(wbase + WARR_U32 * 3);
    stage_W(w1h, W1h, t);
    stage_W(w1l, W1l, t);
    stage_W(w2h, W2h, t);
    stage_W(w2l, W2l, t);
    asm volatile("cp.async.commit_group;" ::: "memory");

    uint32_t aoff[2], boff[2];
#pragma unroll
    for (int mt = 0; mt < 2; mt++) {
        int row = wm * 32 + mt * 16 + ((lane >> 3) & 1) * 8 + (lane & 7);
        aoff[mt] = row * 272 + (lane >> 4) * 16;
    }
#pragma unroll
    for (int np = 0; np < 2; np++) {
        int row = wn * 32 + np * 16 + (lane >> 4) * 8 + (lane & 7);
        boff[np] = row * 272 + ((lane >> 3) & 1) * 16;
    }
    const uint32_t Ahi = smem_u32(As_hi), Alo = smem_u32(As_lo);
    const int lg = lane >> 2;
    const int c2 = (lane & 3) * 2;
    const int srow = t2 >> 2, sq = t2 & 3;
    const int bid = 1 + grp;

    int tile = blockIdx.x * 2 + grp;
    const int step = gridDim.x * 2;
    float4 px[8];
    prefetch_A(A, tile * 64 + srow, sq, px);
    asm volatile("cp.async.wait_group 0;" ::: "memory");
    __syncthreads();

    for (; tile < NT64; tile += step) {
        const int row0 = tile * 64;
        const int gr = row0 + srow;

        // stage current tile from registers (+agg +affine +combine)
        {
            const float4* Gr = reinterpret_cast<const float4*>(g_agg + (size_t)gr * D);
#pragma unroll
            for (int j = 0; j < 8; j++) {
                int f4 = sq * 8 + j;
                float4 v = make_float4(0.f, 0.f, 0.f, 0.f);
                if (gr < N_NODES) {
                    v = px[j];
                    if (AFF) {
                        float4 a = *reinterpret_cast<const float4*>(g_bn + f4 * 4);
                        float4 c = *reinterpret_cast<const float4*>(g_bn + D + f4 * 4);
                        v.x = a.x * v.x + c.x; v.y = a.y * v.y + c.y;
                        v.z = a.z * v.z + c.z; v.w = a.w * v.w + c.w;
                    }
                    float4 q4 = Gr[f4];
                    v.x = cA * v.x + q4.x; v.y = cA * v.y + q4.y;
                    v.z = cA * v.z + q4.z; v.w = cA * v.w + q4.w;
                }
                uint32_t h0, l0, h1, l1;
                split2(v.x, v.y, h0, l0);
                split2(v.z, v.w, h1, l1);
                int o = srow * HROW_U32 + f4 * 2;
                *reinterpret_cast<uint2*>(&As_hi[o]) = make_uint2(h0, h1);
                *reinterpret_cast<uint2*>(&As_lo[o]) = make_uint2(l0, l1);
            }
        }
        barg(bid);

        float acc[2][4][4];
#pragma unroll
        for (int mt = 0; mt < 2; mt++)
#pragma unroll
            for (int nt = 0; nt < 4; nt++)
#pragma unroll
                for (int i = 0; i < 4; i++) acc[mt][nt][i] = 0.f;

        // ---- GEMM1 ----
        mma_3pass(acc, Ahi, Alo, W1h, W1l, aoff, boff);

        const int ntile = tile + step;
        if (ntile < NT64) prefetch_A(A, ntile * 64 + srow, sq, px);

        barg(bid);

        // epilogue1: P = relu(acc+b1) -> bf16 hi/lo back into As
#pragma unroll
        for (int mt = 0; mt < 2; mt++) {
            int ra = wm * 32 + mt * 16 + lg;
            int rb = ra + 8;
#pragma unroll
            for (int nt = 0; nt < 4; nt++) {
                int col = wn * 32 + nt * 8 + c2;
                int o = col >> 1;
                float t0 = fmaxf(acc[mt][nt][0] + sb1[col], 0.f);
                float t1 = fmaxf(acc[mt][nt][1] + sb1[col + 1], 0.f);
                float t2v = fmaxf(acc[mt][nt][2] + sb1[col], 0.f);
                float t3 = fmaxf(acc[mt][nt][3] + sb1[col + 1], 0.f);
                uint32_t hi, lo;
                split2(t0, t1, hi, lo);
                As_hi[ra * HROW_U32 + o] = hi;
                As_lo[ra * HROW_U32 + o] = lo;
                split2(t2v, t3, hi, lo);
                As_hi[rb * HROW_U32 + o] = hi;
                As_lo[rb * HROW_U32 + o] = lo;
#pragma unroll
                for (int i = 0; i < 4; i++) acc[mt][nt][i] = 0.f;
            }
        }
        barg(bid);

        // ---- GEMM2 ----
        mma_3pass(acc, Ahi, Alo, W2h, W2l, aoff, boff);
        barg(bid);

        // epilogue2: relu+bias, store h, accumulate column stats
        {
            float sp[4][2], qp[4][2];
#pragma unroll
            for (int nt = 0; nt < 4; nt++) {
                sp[nt][0] = sp[nt][1] = 0.f;
                qp[nt][0] = qp[nt][1] = 0.f;
            }
#pragma unroll
            for (int mt = 0; mt < 2; mt++) {
                int ra = row0 + wm * 32 + mt * 16 + lg;
                int rb = ra + 8;
#pragma unroll
                for (int nt = 0; nt < 4; nt++) {
                    int col = wn * 32 + nt * 8 + c2;
                    float v0 = fmaxf(acc[mt][nt][0] + sb2[col], 0.f);
                    float v1 = fmaxf(acc[mt][nt][1] + sb2[col + 1], 0.f);
                    float v2 = fmaxf(acc[mt][nt][2] + sb2[col], 0.f);
                    float v3 = fmaxf(acc[mt][nt][3] + sb2[col + 1], 0.f);
                    if (ra < N_NODES) {
                        *reinterpret_cast<float2*>(out + (size_t)ra * D + col) =
                            make_float2(v0, v1);
                        sp[nt][0] += v0; sp[nt][1] += v1;
                        qp[nt][0] += v0 * v0; qp[nt][1] += v1 * v1;
                    }
                    if (rb < N_NODES) {
                        *reinterpret_cast<float2*>(out + (size_t)rb * D + col) =
                            make_float2(v2, v3);
                        sp[nt][0] += v2; sp[nt][1] += v3;
                        qp[nt][0] += v2 * v2; qp[nt][1] += v3 * v3;
                    }
                }
            }
#pragma unroll
            for (int nt = 0; nt < 4; nt++) {
#pragma unroll
                for (int d = 4; d < 32; d <<= 1) {
                    sp[nt][0] += __shfl_xor_sync(0xffffffffu, sp[nt][0], d);
                    sp[nt][1] += __shfl_xor_sync(0xffffffffu, sp[nt][1], d);
                    qp[nt][0] += __shfl_xor_sync(0xffffffffu, qp[nt][0], d);
                    qp[nt][1] += __shfl_xor_sync(0xffffffffu, qp[nt][1], d);
                }
            }
            if (lg == 0) {
#pragma unroll
                for (int nt = 0; nt < 4; nt++) {
                    int col = wn * 32 + nt * 8 + c2;
                    atomicAdd(&s_sum[col], sp[nt][0]);
                    atomicAdd(&s_sum[col + 1], sp[nt][1]);
                    atomicAdd(&s_sq[col], qp[nt][0]);
                    atomicAdd(&s_sq[col + 1], qp[nt][1]);
                }
            }
        }
    }

    __syncthreads();
    if (t < D) {
        asm volatile("red.global.add.f32 [%0], %1;" :: "l"(&g_colsum[t]), "f"(s_sum[t]) : "memory");
        asm volatile("red.global.add.f32 [%0], %1;" :: "l"(&g_colsq[t]), "f"(s_sq[t]) : "memory");
    }
}

// ---------------------------------------------------------------------------
// Persistent final linear, dual-group
// ---------------------------------------------------------------------------
__global__ void __launch_bounds__(512) k_gemm_l(const float* __restrict__ A,
                                                const float* __restrict__ bias,
                                                const __nv_bfloat16* __restrict__ wh,
                                                const __nv_bfloat16* __restrict__ wl,
                                                float* __restrict__ out) {
    extern __shared__ uint32_t smem[];
    __shared__ float sb[D];

    const int t = threadIdx.x;
    const int grp = t >> 8;
    const int t2 = t & 255;
    const int warp8 = t2 >> 5, lane = t & 31;
    const int wm = warp8 & 1, wn = warp8 >> 1;

    uint32_t* As_hi = smem + grp * 2 * HARR_U32;
    uint32_t* As_lo = As_hi + HARR_U32;
    uint32_t* wbase = smem + 4 * HARR_U32;

    if (t < D) sb[t] = __ldg(bias + t);

    const uint32_t Wh = smem_u32(wbase);
    const uint32_t Wl = smem_u32(wbase + WARR_U32);
    stage_W(wh, Wh, t);
    stage_W(wl, Wl, t);
    asm volatile("cp.async.commit_group;" ::: "memory");

    uint32_t aoff[2], boff[2];
#pragma unroll
    for (int mt = 0; mt < 2; mt++) {
        int row = wm * 32 + mt * 16 + ((lane >> 3) & 1) * 8 + (lane & 7);
        aoff[mt] = row * 272 + (lane >> 4) * 16;
    }
#pragma unroll
    for (int np = 0; np < 2; np++) {
        int row = wn * 32 + np * 16 + (lane >> 4) * 8 + (lane & 7);
        boff[np] = row * 272 + ((lane >> 3) & 1) * 16;
    }
    const uint32_t Ahi = smem_u32(As_hi), Alo = smem_u32(As_lo);
    const int lg = lane >> 2;
    const int c2 = (lane & 3) * 2;
    const int srow = t2 >> 2, sq = t2 & 3;
    const int bid = 1 + grp;

    int tile = blockIdx.x * 2 + grp;
    const int step = gridDim.x * 2;
    float4 px[8];
    prefetch_A(A, tile * 64 + srow, sq, px);
    asm volatile("cp.async.wait_group 0;" ::: "memory");
    __syncthreads();

    for (; tile < NT64; tile += step) {
        const int row0 = tile * 64;
        const int gr = row0 + srow;

#pragma unroll
        for (int j = 0; j < 8; j++) {
            int f4 = sq * 8 + j;
            float4 v = make_float4(0.f, 0.f, 0.f, 0.f);
            if (gr < N_NODES) {
                v = px[j];
                float4 a = *reinterpret_cast<const float4*>(g_bn + f4 * 4);
                float4 c = *reinterpret_cast<const float4*>(g_bn + D + f4 * 4);
                v.x = a.x * v.x + c.x; v.y = a.y * v.y + c.y;
                v.z = a.z * v.z + c.z; v.w = a.w * v.w + c.w;
            }
            uint32_t h0, l0, h1, l1;
            split2(v.x, v.y, h0, l0);
            split2(v.z, v.w, h1, l1);
            int o = srow * HROW_U32 + f4 * 2;
            *reinterpret_cast<uint2*>(&As_hi[o]) = make_uint2(h0, h1);
            *reinterpret_cast<uint2*>(&As_lo[o]) = make_uint2(l0, l1);
        }
        barg(bid);

        float acc[2][4][4];
#pragma unroll
        for (int mt = 0; mt < 2; mt++)
#pragma unroll
            for (int nt = 0; nt < 4; nt++)
#pragma unroll
                for (int i = 0; i < 4; i++) acc[mt][nt][i] = 0.f;

        mma_3pass(acc, Ahi, Alo, Wh, Wl, aoff, boff);

        const int ntile = tile + step;
        if (ntile < NT64) prefetch_A(A, ntile * 64 + srow, sq, px);

        barg(bid);

#pragma unroll
        for (int mt = 0; mt < 2; mt++) {
            int ra = row0 + wm * 32 + mt * 16 + lg;
            int rb = ra + 8;
#pragma unroll
            for (int nt = 0; nt < 4; nt++) {
                int col = wn * 32 + nt * 8 + c2;
                if (ra < N_NODES)
                    *reinterpret_cast<float2*>(out + (size_t)ra * D + col) =
                        make_float2(fmaxf(acc[mt][nt][0] + sb[col], 0.f),
                                    fmaxf(acc[mt][nt][1] + sb[col + 1], 0.f));
                if (rb < N_NODES)
                    *reinterpret_cast<float2*>(out + (size_t)rb * D + col) =
                        make_float2(fmaxf(acc[mt][nt][2] + sb[col], 0.f),
                                    fmaxf(acc[mt][nt][3] + sb[col + 1], 0.f));
            }
        }
    }
}

// ---------------------------------------------------------------------------
// BN prep: compute affine, then re-zero stats for next layer
// ---------------------------------------------------------------------------
__global__ void k_bnprep(const float* __restrict__ gamma,
                         const float* __restrict__ beta) {
    int t = threadIdx.x;
    float inv_n = 1.0f / (float)N_NODES;
    float mu = g_colsum[t] * inv_n;
    float var = g_colsq[t] * inv_n - mu * mu;
    float a = gamma[t] * rsqrtf(var + 1e-5f);
    g_bn[t] = a;
    g_bn[D + t] = beta[t] - mu * a;
    g_colsum[t] = 0.f;
    g_colsq[t] = 0.f;
}

// ---------------------------------------------------------------------------
__global__ void __launch_bounds__(256) k_pairs(const float* __restrict__ h,
                                               const int* __restrict__ pairs,
                                               const float* __restrict__ Wfc,
                                               const float* __restrict__ bfc,
                                               float* __restrict__ out) {
    __shared__ float sW[O_OUT][D];
    __shared__ float sb[O_OUT];
    int t = threadIdx.x;
    for (int i = t; i < O_OUT * D; i += 256) sW[i / D][i % D] = Wfc[i];
    if (t < O_OUT) sb[t] = bfc[t];
    __syncthreads();

    int p = (blockIdx.x * 256 + t) >> 5;
    int lane = t & 31;
    if (p >= P_PAIRS) return;

    int i0 = pairs[2 * p];
    int i1 = pairs[2 * p + 1];
    float4 u = reinterpret_cast<const float4*>(h + (size_t)i0 * D)[lane];
    float4 v = reinterpret_cast<const float4*>(h + (size_t)i1 * D)[lane];
    float4 w = make_float4(u.x * v.x, u.y * v.y, u.z * v.z, u.w * v.w);

    float s[O_OUT];
#pragma unroll
    for (int o = 0; o < O_OUT; o++)
        s[o] = w.x * sW[o][4 * lane + 0] + w.y * sW[o][4 * lane + 1] +
               w.z * sW[o][4 * lane + 2] + w.w * sW[o][4 * lane + 3];
#pragma unroll
    for (int o = 0; o < O_OUT; o++)
#pragma unroll
        for (int off = 16; off > 0; off >>= 1)
            s[o] += __shfl_xor_sync(0xffffffffu, s[o], off);
    if (lane == 0)
#pragma unroll
        for (int o = 0; o < O_OUT; o++) out[(size_t)p * O_OUT + o] = s[o] + sb[o];
}

// ---------------------------------------------------------------------------
extern "C" void kernel_launch(void* const* d_in, const int* in_sizes, int n_in,
                              void* d_out, int out_size) {
    const float* x    = (const float*)d_in[0];
    const float* W1a  = (const float*)d_in[1];
    const float* b1a  = (const float*)d_in[2];
    const float* W2a  = (const float*)d_in[3];
    const float* b2a  = (const float*)d_in[4];
    const float* g0   = (const float*)d_in[5];
    const float* bt0  = (const float*)d_in[6];
    const float* eps0 = (const float*)d_in[7];
    const float* W1b  = (const float*)d_in[8];
    const float* b1b  = (const float*)d_in[9];
    const float* W2b  = (const float*)d_in[10];
    const float* b2b  = (const float*)d_in[11];
    const float* g1   = (const float*)d_in[12];
    const float* bt1  = (const float*)d_in[13];
    const float* eps1 = (const float*)d_in[14];
    const float* Wl   = (const float*)d_in[15];
    const float* bl   = (const float*)d_in[16];
    const float* Wfc  = (const float*)d_in[17];
    const float* bfc  = (const float*)d_in[18];
    const int* esrc   = (const int*)d_in[19];
    const int* edst   = (const int*)d_in[20];
    const int* pairs  = (const int*)d_in[21];
    float* out = (float*)d_out;

    float *t, *h;
    __nv_bfloat16 *wh, *wl;
    cudaGetSymbolAddress((void**)&t, g_t);
    cudaGetSymbolAddress((void**)&h, g_h);
    cudaGetSymbolAddress((void**)&wh, g_wh);
    cudaGetSymbolAddress((void**)&wl, g_wl);

    cudaFuncSetAttribute(k_mlp<0>, cudaFuncAttributeMaxDynamicSharedMemorySize, SMEM_MLP);
    cudaFuncSetAttribute(k_mlp<1>, cudaFuncAttributeMaxDynamicSharedMemorySize, SMEM_MLP);
    cudaFuncSetAttribute(k_gemm_l, cudaFuncAttributeMaxDynamicSharedMemorySize, SMEM_GL);

    const int EB = (E_EDGES + 255) / 256;
    const int GB = (N_NODES * 32 + 255) / 256;   // gather: warp per node
    const int PB = (P_PAIRS * 32) / 256;
    const int WS = D * D;
    const int PG = 148;

    // prep + CSR build (once per launch)
    k_prep_w<<<(5 * WS + 255) / 256, 256>>>(W1a, W2a, W1b, W2b, Wl);
    k_hist<<<EB, 256>>>(edst);
    k_scan<<<1, 1024>>>();
    k_fill<<<EB, 256>>>(esrc, edst);

    // Layer A
    k_gather<0><<<GB, 256>>>(x);
    k_mlp<0><<<PG, 512, SMEM_MLP>>>(x, eps0, b1a, b2a,
                                    wh + 0 * WS, wl + 0 * WS,
                                    wh + 1 * WS, wl + 1 * WS, h);
    k_bnprep<<<1, 128>>>(g0, bt0);

    // Layer B (BN-A affine folded into gather + mlp stage)
    k_gather<1><<<GB, 256>>>(h);
    k_mlp<1><<<PG, 512, SMEM_MLP>>>(h, eps1, b1b, b2b,
                                    wh + 2 * WS, wl + 2 * WS,
                                    wh + 3 * WS, wl + 3 * WS, h);
    k_bnprep<<<1, 128>>>(g1, bt1);

    // Final linear (BN-B affine folded) + pair head
    k_gemm_l<<<PG, 512, SMEM_GL>>>(h, bl, wh + 4 * WS, wl + 4 * WS, t);
    k_pairs<<<PB, 256>>>(t, pairs, Wfc, bfc, out);
}